// round 6
// baseline (speedup 1.0000x reference)
#include <cuda_runtime.h>
#include <cub/cub.cuh>
#include <math.h>
#include <stdint.h>

#define NSCALE 2
#define NPTS   240000
#define NVOX   80000
#define NPB    120000
#define MPB    30000
#define HDIM   64
#define CDIM   20
#define MIDD   16
#define HIDD   128
#define NIMG   60000
#define CUBTEMP_BYTES (24u*1024u*1024u)
#define QLEV   262143.0f   // 18-bit linear err quantization

// ------------------------- static device scratch (per-scale sets) -------------------------
__device__ float g_H1[NSCALE][(size_t)NVOX * HIDD];
__device__ float g_pred3d[NSCALE][(size_t)NVOX * CDIM];
__device__ int   g_counts[NSCALE][(size_t)NVOX * CDIM];
__device__ int   g_voxlab[NSCALE][NVOX];
__device__ int   g_idx[NSCALE][NIMG];
__device__ float g_P[NSCALE][(size_t)NIMG * HDIM];
__device__ float g_a1[NSCALE][(size_t)NIMG * MIDD];
__device__ float g_a2[NSCALE][(size_t)NIMG * MIDD];
__device__ float g_attw[NSCALE][(size_t)NIMG * 2];
__device__ float g_y1[NSCALE][(size_t)NIMG * HDIM];
__device__ float g_y2[NSCALE][(size_t)NIMG * HDIM];
__device__ float g_fpred[NSCALE][(size_t)NIMG * CDIM];
__device__ float g_stats[NSCALE][4 * HDIM];
__device__ uint32_t g_keys_in[NSCALE][(size_t)CDIM * NVOX];
__device__ uint32_t g_keys_out[NSCALE][(size_t)CDIM * NVOX];
__device__ int    g_gts_vox[NSCALE][CDIM];
__device__ double g_classLoss[NSCALE][CDIM];
__device__ unsigned char g_cubtemp[NSCALE][CUBTEMP_BYTES];
// final-classifier private buffers
__device__ uint32_t g_keysF_in[(size_t)CDIM * NIMG];
__device__ uint32_t g_keysF_out[(size_t)CDIM * NIMG];
__device__ double g_classLossF[CDIM];
__device__ unsigned char g_cubtempF[CUBTEMP_BYTES];
__device__ float g_HF[(size_t)NIMG * HIDD];
__device__ float g_fpredF[(size_t)NIMG * CDIM];
__device__ float g_feats[(size_t)NIMG * 2 * HDIM];   // disjoint column slices per scale
__device__ int    g_gts_img[CDIM];
__device__ double g_loss;

// ------------------------- reduction helper -------------------------
__device__ __forceinline__ double blockReduceSumD(double v) {
    __shared__ double sh[32];
    int lane = threadIdx.x & 31, wid = threadIdx.x >> 5;
#pragma unroll
    for (int o = 16; o > 0; o >>= 1) v += __shfl_down_sync(0xffffffffu, v, o);
    if (lane == 0) sh[wid] = v;
    __syncthreads();
    int nw = (blockDim.x + 31) >> 5;
    v = (threadIdx.x < nw) ? sh[threadIdx.x] : 0.0;
    if (wid == 0) {
#pragma unroll
        for (int o = 16; o > 0; o >>= 1) v += __shfl_down_sync(0xffffffffu, v, o);
    }
    return v;  // valid on thread 0
}

// ------------------------- elementwise kernels -------------------------
__global__ void k_scatter(const int* __restrict__ coors_s, const int* __restrict__ labels,
                          int* __restrict__ counts) {
    int i = blockIdx.x * blockDim.x + threadIdx.x;
    if (i < NPTS) atomicAdd(&counts[(size_t)coors_s[i] * CDIM + labels[i]], 1);
}

__global__ void k_argmax(const int* __restrict__ counts, int* __restrict__ voxlab,
                         int* __restrict__ gts) {
    __shared__ int h[CDIM];
    if (threadIdx.x < CDIM) h[threadIdx.x] = 0;
    __syncthreads();
    int v = blockIdx.x * blockDim.x + threadIdx.x;
    if (v < NVOX) {
        const int* row = counts + (size_t)v * CDIM;
        int best = row[0], bi = 0;
#pragma unroll
        for (int c = 1; c < CDIM; c++) { int x = row[c]; if (x > best) { best = x; bi = c; } }
        voxlab[v] = bi;
        atomicAdd(&h[bi], 1);
    }
    __syncthreads();
    if (threadIdx.x < CDIM && h[threadIdx.x]) atomicAdd(&gts[threadIdx.x], h[threadIdx.x]);
}

__global__ void k_hist(const int* __restrict__ lab, int n, int* __restrict__ gts) {
    __shared__ int h[CDIM];
    if (threadIdx.x < CDIM) h[threadIdx.x] = 0;
    __syncthreads();
    int i = blockIdx.x * blockDim.x + threadIdx.x;
    if (i < n) atomicAdd(&h[lab[i]], 1);
    __syncthreads();
    if (threadIdx.x < CDIM && h[threadIdx.x]) atomicAdd(&gts[threadIdx.x], h[threadIdx.x]);
}

__global__ void k_idxgather(const float* __restrict__ pts_s, const int* __restrict__ coors_s,
                            const int* __restrict__ p2img, int* __restrict__ idxArr,
                            float* __restrict__ P) {
    int t = blockIdx.x * blockDim.x + threadIdx.x;
    if (t < NIMG * HDIM) {
        int r = t >> 6, c = t & 63;
        int b = r / MPB;
        int vi = coors_s[b * NPB + p2img[r]];
        if (c == 0) idxArr[r] = vi;
        P[t] = pts_s[(size_t)vi * HDIM + c];
    }
}

__global__ void k_att(const float* __restrict__ a1, const float* __restrict__ a2,
                      float* __restrict__ attw,
                      const float* __restrict__ fc3w, const float* __restrict__ fc3b) {
    int r = blockIdx.x * blockDim.x + threadIdx.x;
    if (r >= NIMG) return;
    float z0 = fc3b[0], z1 = fc3b[1];
#pragma unroll
    for (int j = 0; j < MIDD; j++) {
        float v = a1[(size_t)r * MIDD + j];
        z0 += v * fc3w[j * 2 + 0];
        z1 += v * fc3w[j * 2 + 1];
    }
#pragma unroll
    for (int j = 0; j < MIDD; j++) {
        float v = a2[(size_t)r * MIDD + j];
        z0 += v * fc3w[(MIDD + j) * 2 + 0];
        z1 += v * fc3w[(MIDD + j) * 2 + 1];
    }
    attw[2 * r + 0] = 1.f / (1.f + expf(-z0));
    attw[2 * r + 1] = 1.f / (1.f + expf(-z1));
}

#define ROWSPB 512
__global__ void k_colstats(const float* __restrict__ y, float* __restrict__ stats, int statsOff) {
    const int col = threadIdx.x & 63;
    const int grp = threadIdx.x >> 6;  // 0..3
    float s = 0.f, q = 0.f;
    int r0 = blockIdx.x * ROWSPB;
    int rend = r0 + ROWSPB; if (rend > NIMG) rend = NIMG;
    for (int r = r0 + grp; r < rend; r += 4) {
        float v = y[(size_t)r * HDIM + col];
        s += v; q += v * v;
    }
    __shared__ float sh[2][4][64];
    sh[0][grp][col] = s; sh[1][grp][col] = q;
    __syncthreads();
    if (grp == 0) {
        s = sh[0][0][col] + sh[0][1][col] + sh[0][2][col] + sh[0][3][col];
        q = sh[1][0][col] + sh[1][1][col] + sh[1][2][col] + sh[1][3][col];
        atomicAdd(&stats[statsOff + col], s);
        atomicAdd(&stats[statsOff + 64 + col], q);
    }
}

__global__ void k_fuse(const float* __restrict__ y1, const float* __restrict__ y2,
                       const float* __restrict__ attw, const float* __restrict__ stats,
                       const float* __restrict__ g1, const float* __restrict__ b1,
                       const float* __restrict__ g2, const float* __restrict__ b2, int s) {
    int t = blockIdx.x * blockDim.x + threadIdx.x;
    if (t >= NIMG * HDIM) return;
    int r = t >> 6, c = t & 63;
    const float n = (float)NIMG;
    float mu1 = stats[c] / n;        float var1 = stats[64 + c] / n - mu1 * mu1;
    float mu2 = stats[128 + c] / n;  float var2 = stats[192 + c] / n - mu2 * mu2;
    float v1 = fmaxf((y1[t] - mu1) * rsqrtf(var1 + 1e-5f) * g1[c] + b1[c], 0.f);
    float v2 = fmaxf((y2[t] - mu2) * rsqrtf(var2 + 1e-5f) * g2[c] + b2[c], 0.f);
    g_feats[(size_t)r * (2 * HDIM) + s * HDIM + c] = v1 * attw[2 * r] + v2 * attw[2 * r + 1];
}

// ------------------------- big GEMM (f32x2): C = act(A[M,K] @ W[K,N] + bias) -------------------------
template <int BM, int BN, int TM, int TN, bool RELU>
__global__ void __launch_bounds__(256) k_gemm2(const float* __restrict__ A, int lda,
                                               const float* __restrict__ W,
                                               const float* __restrict__ bias,
                                               float* __restrict__ Cm,
                                               int M, int N, int K) {
    constexpr int TX = BN / TN;
    constexpr int TY = BM / TM;
    static_assert(TX * TY == 256 && TM == 8 && (TN == 4 || TN == 8), "bad tile");
    __shared__ __align__(16) float As[16][BM + 4];
    __shared__ __align__(16) float Ws[16][BN + 4];
    const int bm = blockIdx.y * BM, bn = blockIdx.x * BN;
    const int tid = threadIdx.x;
    const int tx = tid % TX, ty = tid / TX;
    unsigned long long acc[TM][TN / 2] = {};
    for (int k0 = 0; k0 < K; k0 += 16) {
#pragma unroll
        for (int it = 0; it < BM / 64; it++) {
            int g = tid + it * 256;
            int m = g >> 2, q = g & 3;
            int gm = bm + m;
            float4 v = make_float4(0.f, 0.f, 0.f, 0.f);
            if (gm < M) v = *(const float4*)&A[(size_t)gm * lda + k0 + 4 * q];
            As[4 * q + 0][m] = v.x; As[4 * q + 1][m] = v.y;
            As[4 * q + 2][m] = v.z; As[4 * q + 3][m] = v.w;
        }
#pragma unroll
        for (int it = 0; it < BN / 64; it++) {
            int g = tid + it * 256;
            int kk = g / (BN / 4), nq = g % (BN / 4);
            *(float4*)&Ws[kk][4 * nq] = *(const float4*)&W[(size_t)(k0 + kk) * N + bn + 4 * nq];
        }
        __syncthreads();
#pragma unroll
        for (int kk = 0; kk < 16; kk++) {
            float a[TM];
            *(float4*)&a[0] = *(const float4*)&As[kk][ty * TM];
            *(float4*)&a[4] = *(const float4*)&As[kk][ty * TM + 4];
            unsigned long long b2[TN / 2];
            *(ulonglong2*)&b2[0] = *(const ulonglong2*)&Ws[kk][tx * TN];
            if constexpr (TN == 8) {
                *(ulonglong2*)&b2[2] = *(const ulonglong2*)&Ws[kk][tx * TN + 4];
            }
#pragma unroll
            for (int i = 0; i < TM; i++) {
                unsigned long long a2;
                asm("mov.b64 %0, {%1, %1};" : "=l"(a2) : "f"(a[i]));
#pragma unroll
                for (int j = 0; j < TN / 2; j++)
                    asm("fma.rn.f32x2 %0, %1, %2, %0;" : "+l"(acc[i][j]) : "l"(a2), "l"(b2[j]));
            }
        }
        __syncthreads();
    }
#pragma unroll
    for (int i = 0; i < TM; i++) {
        int gm = bm + ty * TM + i;
        if (gm >= M) continue;
#pragma unroll
        for (int j = 0; j < TN / 2; j++) {
            int gn = bn + tx * TN + 2 * j;
            float lo = __uint_as_float((unsigned)(acc[i][j] & 0xFFFFFFFFull)) + bias[gn];
            float hi = __uint_as_float((unsigned)(acc[i][j] >> 32)) + bias[gn + 1];
            if (RELU) { lo = fmaxf(lo, 0.f); hi = fmaxf(hi, 0.f); }
            *(float2*)&Cm[(size_t)gm * N + gn] = make_float2(lo, hi);
        }
    }
}

// ------------------------- small-N GEMM (scalar) -------------------------
template <int BM, int BN, int TM, int TN, bool RELU>
__global__ void __launch_bounds__(256) k_gemm(const float* __restrict__ A, int lda,
                                              const float* __restrict__ W,
                                              const float* __restrict__ bias,
                                              float* __restrict__ Cm,
                                              int M, int N, int K) {
    constexpr int TX = BN / TN;
    constexpr int TY = BM / TM;
    static_assert(TX * TY == 256, "bad tile");
    __shared__ __align__(16) float As[16][BM + 4];
    __shared__ __align__(16) float Ws[16][BN + 4];
    const int bm = blockIdx.y * BM, bn = blockIdx.x * BN;
    const int tid = threadIdx.x;
    const int tx = tid % TX, ty = tid / TX;
    float acc[TM][TN] = {};
    for (int k0 = 0; k0 < K; k0 += 16) {
#pragma unroll
        for (int e = tid; e < BM * 16; e += 256) {
            int m = e >> 4, kk = e & 15;
            int gm = bm + m;
            As[kk][m] = (gm < M) ? A[(size_t)gm * lda + (k0 + kk)] : 0.f;
        }
#pragma unroll
        for (int e = tid; e < BN * 16; e += 256) {
            int kk = e / BN, n2 = e % BN;
            int gn = bn + n2;
            Ws[kk][n2] = (gn < N) ? W[(size_t)(k0 + kk) * N + gn] : 0.f;
        }
        __syncthreads();
#pragma unroll
        for (int kk = 0; kk < 16; kk++) {
            float a[TM], b[TN];
#pragma unroll
            for (int i = 0; i < TM; i++) a[i] = As[kk][ty * TM + i];
#pragma unroll
            for (int j = 0; j < TN; j++) b[j] = Ws[kk][tx * TN + j];
#pragma unroll
            for (int i = 0; i < TM; i++)
#pragma unroll
                for (int j = 0; j < TN; j++) acc[i][j] += a[i] * b[j];
        }
        __syncthreads();
    }
#pragma unroll
    for (int i = 0; i < TM; i++) {
        int gm = bm + ty * TM + i;
        if (gm >= M) continue;
#pragma unroll
        for (int j = 0; j < TN; j++) {
            int gn = bn + tx * TN + j;
            if (gn < N) {
                float v = acc[i][j] + bias[gn];
                if (RELU) v = fmaxf(v, 0.f);
                Cm[(size_t)gm * N + gn] = v;
            }
        }
    }
}

// ------------------------- loss kernels -------------------------
// key = (c << 19) | (q18 << 1) | fg ; q18 = round(err * QLEV)
__global__ void k_softmax_keys(const float* __restrict__ logits, const int* __restrict__ lab,
                               int n, float ce_w, uint32_t* __restrict__ keys) {
    int i = blockIdx.x * blockDim.x + threadIdx.x;
    double ce = 0.0;
    if (i < n) {
        float z[CDIM];
#pragma unroll
        for (int c = 0; c < CDIM; c++) z[c] = logits[(size_t)i * CDIM + c];
        float m = z[0];
#pragma unroll
        for (int c = 1; c < CDIM; c++) m = fmaxf(m, z[c]);
        float se = 0.f;
#pragma unroll
        for (int c = 0; c < CDIM; c++) se += expf(z[c] - m);
        float ls = logf(se);
        int l = lab[i];
        ce = -(double)(z[l] - m - ls);
#pragma unroll
        for (int c = 0; c < CDIM; c++) {
            float p = expf(z[c] - m - ls);
            uint32_t fg = (c == l) ? 1u : 0u;
            float err = fabsf((float)fg - p);
            uint32_t q = (uint32_t)__float2uint_rn(err * QLEV);
            if (q > 262143u) q = 262143u;
            keys[(size_t)c * n + i] = ((uint32_t)c << 19) | (q << 1) | fg;
        }
    }
    double tot = blockReduceSumD(ce);
    if (threadIdx.x == 0) atomicAdd(&g_loss, tot * (double)ce_w / (double)n);
}

// one block per class over its sorted (ascending) segment; iterate descending err
__global__ void __launch_bounds__(1024) k_lovasz(const uint32_t* __restrict__ keysAll,
                                                 const int* __restrict__ gts,
                                                 double* __restrict__ classLoss, int n) {
    int c = blockIdx.x;
    int tid = threadIdx.x, lane = tid & 31, wid = tid >> 5;
    const uint32_t* keys = keysAll + (size_t)c * n;
    float g = (float)gts[c];
    __shared__ int shWs[32];
    __shared__ double shD[32];
    int carry = 0;
    double acc = 0.0;
    for (int pos0 = 0; pos0 < n; pos0 += 1024) {
        int pos = pos0 + tid;
        int f = 0; float e = 0.f;
        if (pos < n) {
            uint32_t k = keys[n - 1 - pos];   // descending err
            f = (int)(k & 1u);
            e = (float)((k >> 1) & 0x3FFFFu) * (1.0f / QLEV);
        }
        unsigned bal = __ballot_sync(0xffffffffu, f);
        int inclw = __popc(bal & (0xFFFFFFFFu >> (31 - lane)));
        if (lane == 31) shWs[wid] = inclw;
        __syncthreads();
        if (wid == 0) {
            int v = shWs[lane];
#pragma unroll
            for (int o = 1; o < 32; o <<= 1) {
                int u = __shfl_up_sync(0xffffffffu, v, o);
                if (lane >= o) v += u;
            }
            shWs[lane] = v;
        }
        __syncthreads();
        int cf = carry + inclw + (wid > 0 ? shWs[wid - 1] : 0);
        int total = shWs[31];
        if (pos < n) {
            float fi = (float)pos + 1.f;
            float cff = (float)cf;
            float jac = 1.f - (g - cff) / (g + fi - cff);
            float jacp = 0.f;
            if (pos > 0) {
                float cfp = cff - (float)f;
                jacp = 1.f - (g - cfp) / (g + (fi - 1.f) - cfp);
            }
            acc += (double)(e * (jac - jacp));
        }
        carry += total;
        __syncthreads();
    }
#pragma unroll
    for (int o = 16; o > 0; o >>= 1) acc += __shfl_down_sync(0xffffffffu, acc, o);
    if (lane == 0) shD[wid] = acc;
    __syncthreads();
    if (wid == 0) {
        double v = shD[lane];
#pragma unroll
        for (int o = 16; o > 0; o >>= 1) v += __shfl_down_sync(0xffffffffu, v, o);
        if (tid == 0) classLoss[c] = v;
    }
}

__global__ void k_lovreduce(float w, const int* __restrict__ gts,
                            const double* __restrict__ classLoss) {
    int tid = threadIdx.x;
    double s = 0.0; int pc = 0;
    if (tid < CDIM && gts[tid] > 0) { s = classLoss[tid]; pc = 1; }
#pragma unroll
    for (int o = 16; o > 0; o >>= 1) {
        s += __shfl_down_sync(0xffffffffu, s, o);
        pc += __shfl_down_sync(0xffffffffu, pc, o);
    }
    if (tid == 0) {
        int d = pc > 0 ? pc : 1;
        atomicAdd(&g_loss, (double)w * s / (double)d);
    }
}

__global__ void k_kl(double w, const float* __restrict__ fpred,
                     const float* __restrict__ pred3d, const int* __restrict__ idxArr) {
    int r = blockIdx.x * blockDim.x + threadIdx.x;
    double local = 0.0;
    if (r < NIMG) {
        float zf[CDIM], zp[CDIM];
        int vi = idxArr[r];
#pragma unroll
        for (int c = 0; c < CDIM; c++) {
            zf[c] = fpred[(size_t)r * CDIM + c];
            zp[c] = pred3d[(size_t)vi * CDIM + c];
        }
        float mf = zf[0], mp = zp[0];
#pragma unroll
        for (int c = 1; c < CDIM; c++) { mf = fmaxf(mf, zf[c]); mp = fmaxf(mp, zp[c]); }
        float sf = 0.f, sp = 0.f;
#pragma unroll
        for (int c = 0; c < CDIM; c++) { sf += expf(zf[c] - mf); sp += expf(zp[c] - mp); }
        float lsf = logf(sf), lsp = logf(sp);
        float acc = 0.f;
#pragma unroll
        for (int c = 0; c < CDIM; c++) {
            float lp = zf[c] - mf - lsf;
            float p = expf(lp);
            float lq = zp[c] - mp - lsp;
            acc += p * (lp - lq);
        }
        local = (double)acc;
    }
    double tot = blockReduceSumD(local);
    if (threadIdx.x == 0) atomicAdd(&g_loss, tot * w);
}

__global__ void k_finish(float* out) { out[0] = (float)g_loss; }

// ------------------------- host -------------------------
static inline int ceildiv(int a, int b) { return (a + b - 1) / b; }

extern "C" void kernel_launch(void* const* d_in, const int* in_sizes, int n_in,
                              void* d_out, int out_size) {
    const float* img_feat = (const float*)d_in[0];
    const float* pts_feat = (const float*)d_in[1];
    const int*   coors_inv = (const int*)d_in[2];
    const int*   labels   = (const int*)d_in[3];
    const int*   img_label = (const int*)d_in[4];
    const int*   p2img    = (const int*)d_in[5];
    const float* w3a = (const float*)d_in[6];  const float* b3a = (const float*)d_in[7];
    const float* w3b = (const float*)d_in[8];  const float* b3b = (const float*)d_in[9];
    const float* wfa = (const float*)d_in[10]; const float* bfa = (const float*)d_in[11];
    const float* wfb = (const float*)d_in[12]; const float* bfb = (const float*)d_in[13];
    const float* fc1w = (const float*)d_in[14]; const float* fc1b = (const float*)d_in[15];
    const float* fc2w = (const float*)d_in[16]; const float* fc2b = (const float*)d_in[17];
    const float* fc3w = (const float*)d_in[18]; const float* fc3b = (const float*)d_in[19];
    const float* c1w = (const float*)d_in[20]; const float* c1b = (const float*)d_in[21];
    const float* bn1g = (const float*)d_in[22]; const float* bn1b = (const float*)d_in[23];
    const float* c2w = (const float*)d_in[24]; const float* c2b = (const float*)d_in[25];
    const float* bn2g = (const float*)d_in[26]; const float* bn2b = (const float*)d_in[27];
    const float* clw1 = (const float*)d_in[28]; const float* clb1 = (const float*)d_in[29];
    const float* clw2 = (const float*)d_in[30]; const float* clb2 = (const float*)d_in[31];

    // resolve static scratch
    void *pv;
    cudaGetSymbolAddress(&pv, g_H1);       float* H1b = (float*)pv;
    cudaGetSymbolAddress(&pv, g_pred3d);   float* predb = (float*)pv;
    cudaGetSymbolAddress(&pv, g_counts);   int* countsb = (int*)pv;
    cudaGetSymbolAddress(&pv, g_voxlab);   int* voxlabb = (int*)pv;
    cudaGetSymbolAddress(&pv, g_idx);      int* idxb = (int*)pv;
    cudaGetSymbolAddress(&pv, g_P);        float* Pb = (float*)pv;
    cudaGetSymbolAddress(&pv, g_a1);       float* a1b = (float*)pv;
    cudaGetSymbolAddress(&pv, g_a2);       float* a2b = (float*)pv;
    cudaGetSymbolAddress(&pv, g_attw);     float* attwb = (float*)pv;
    cudaGetSymbolAddress(&pv, g_y1);       float* y1b = (float*)pv;
    cudaGetSymbolAddress(&pv, g_y2);       float* y2b = (float*)pv;
    cudaGetSymbolAddress(&pv, g_fpred);    float* fpredb = (float*)pv;
    cudaGetSymbolAddress(&pv, g_stats);    float* statsb = (float*)pv;
    cudaGetSymbolAddress(&pv, g_keys_in);  uint32_t* kinb = (uint32_t*)pv;
    cudaGetSymbolAddress(&pv, g_keys_out); uint32_t* koutb = (uint32_t*)pv;
    cudaGetSymbolAddress(&pv, g_gts_vox);  int* gtsvoxb = (int*)pv;
    cudaGetSymbolAddress(&pv, g_classLoss);double* clsb = (double*)pv;
    cudaGetSymbolAddress(&pv, g_cubtemp);  unsigned char* tempb = (unsigned char*)pv;
    cudaGetSymbolAddress(&pv, g_keysF_in);  uint32_t* kinF = (uint32_t*)pv;
    cudaGetSymbolAddress(&pv, g_keysF_out); uint32_t* koutF = (uint32_t*)pv;
    cudaGetSymbolAddress(&pv, g_classLossF);double* clsF = (double*)pv;
    cudaGetSymbolAddress(&pv, g_cubtempF);  unsigned char* tempF = (unsigned char*)pv;
    cudaGetSymbolAddress(&pv, g_HF);        float* HF = (float*)pv;
    cudaGetSymbolAddress(&pv, g_fpredF);    float* fpredF = (float*)pv;
    cudaGetSymbolAddress(&pv, g_feats);    float* feats = (float*)pv;
    cudaGetSymbolAddress(&pv, g_gts_img);  int* gtsimg = (int*)pv;
    cudaGetSymbolAddress(&pv, g_loss);     void* p_loss = pv;

    // streams/events: same width as the last PASSING run (2 created streams)
    static cudaStream_t strS[NSCALE] = {};
    static cudaEvent_t evFork = nullptr;
    static cudaEvent_t evPred[NSCALE] = {}, evFpred[NSCALE] = {}, evFeats[NSCALE] = {};
    static cudaEvent_t evEndF[NSCALE] = {};
    if (!strS[0]) {
        for (int s = 0; s < NSCALE; s++) {
            cudaStreamCreateWithFlags(&strS[s], cudaStreamNonBlocking);
            cudaEventCreateWithFlags(&evPred[s], cudaEventDisableTiming);
            cudaEventCreateWithFlags(&evFpred[s], cudaEventDisableTiming);
            cudaEventCreateWithFlags(&evFeats[s], cudaEventDisableTiming);
            cudaEventCreateWithFlags(&evEndF[s], cudaEventDisableTiming);
        }
        cudaEventCreateWithFlags(&evFork, cudaEventDisableTiming);
    }

    cudaStream_t st0 = 0;
    cudaMemsetAsync(p_loss, 0, sizeof(double), st0);
    cudaMemsetAsync(gtsimg, 0, CDIM * sizeof(int), st0);

    // fork the fusion streams
    cudaEventRecord(evFork, st0);
    for (int s = 0; s < NSCALE; s++) cudaStreamWaitEvent(strS[s], evFork, 0);

    auto sort_lovasz = [&](uint32_t* kin, uint32_t* kout, unsigned char* temp,
                           double* cls, int n, float weight, const int* gts, cudaStream_t st) {
        size_t tb = CUBTEMP_BYTES;
        cub::DeviceRadixSort::SortKeys(temp, tb, kin, kout, CDIM * n, 0, 24, st);
        k_lovasz<<<CDIM, 1024, 0, st>>>(kout, gts, cls, n);
        k_lovreduce<<<1, 32, 0, st>>>(weight, gts, cls);
    };

    // ---- fusion/GEMM streams (one per scale) ----
    for (int s = 0; s < NSCALE; s++) {
        cudaStream_t sF = strS[s];
        const float* pts_s = pts_feat + (size_t)s * NVOX * HDIM;
        const float* img_s = img_feat + (size_t)s * NIMG * HDIM;
        const int* coors_s = coors_inv + (size_t)s * NPTS;
        float* H1 = H1b + (size_t)s * NVOX * HIDD;
        float* pred = predb + (size_t)s * NVOX * CDIM;
        int* idxArr = idxb + (size_t)s * NIMG;
        float* P = Pb + (size_t)s * NIMG * HDIM;
        float* a1 = a1b + (size_t)s * NIMG * MIDD;
        float* a2 = a2b + (size_t)s * NIMG * MIDD;
        float* attw = attwb + (size_t)s * NIMG * 2;
        float* y1 = y1b + (size_t)s * NIMG * HDIM;
        float* y2 = y2b + (size_t)s * NIMG * HDIM;
        float* fpred = fpredb + (size_t)s * NIMG * CDIM;
        float* stats = statsb + (size_t)s * 4 * HDIM;

        k_gemm2<128, 128, 8, 8, true><<<dim3(1, ceildiv(NVOX, 128)), 256, 0, sF>>>(
            pts_s, HDIM, w3a + (size_t)s * HDIM * HIDD, b3a + s * HIDD, H1, NVOX, HIDD, HDIM);
        k_gemm<64, 32, 4, 2, false><<<dim3(1, ceildiv(NVOX, 64)), 256, 0, sF>>>(
            H1, HIDD, w3b + (size_t)s * HIDD * CDIM, b3b + s * CDIM, pred, NVOX, CDIM, HIDD);
        cudaEventRecord(evPred[s], sF);

        k_idxgather<<<ceildiv(NIMG * HDIM, 256), 256, 0, sF>>>(pts_s, coors_s, p2img, idxArr, P);
        k_gemm<64, 32, 4, 2, false><<<dim3(1, ceildiv(NIMG, 64)), 256, 0, sF>>>(
            P, HDIM, fc1w + (size_t)s * HDIM * MIDD, fc1b + s * MIDD, a1, NIMG, MIDD, HDIM);
        k_gemm<64, 32, 4, 2, false><<<dim3(1, ceildiv(NIMG, 64)), 256, 0, sF>>>(
            img_s, HDIM, fc2w + (size_t)s * HDIM * MIDD, fc2b + s * MIDD, a2, NIMG, MIDD, HDIM);
        k_att<<<ceildiv(NIMG, 256), 256, 0, sF>>>(a1, a2, attw,
            fc3w + (size_t)s * 2 * MIDD * 2, fc3b + s * 2);
        k_gemm2<128, 64, 8, 4, false><<<dim3(1, ceildiv(NIMG, 128)), 256, 0, sF>>>(
            P, HDIM, c1w + (size_t)s * HDIM * HDIM, c1b + s * HDIM, y1, NIMG, HDIM, HDIM);
        k_gemm2<128, 64, 8, 4, false><<<dim3(1, ceildiv(NIMG, 128)), 256, 0, sF>>>(
            img_s, HDIM, c2w + (size_t)s * HDIM * HDIM, c2b + s * HDIM, y2, NIMG, HDIM, HDIM);
        cudaMemsetAsync(stats, 0, 4 * HDIM * sizeof(float), sF);
        k_colstats<<<ceildiv(NIMG, ROWSPB), 256, 0, sF>>>(y1, stats, 0);
        k_colstats<<<ceildiv(NIMG, ROWSPB), 256, 0, sF>>>(y2, stats, 128);
        k_fuse<<<ceildiv(NIMG * HDIM, 256), 256, 0, sF>>>(y1, y2, attw, stats,
            bn1g + s * HDIM, bn1b + s * HDIM, bn2g + s * HDIM, bn2b + s * HDIM, s);
        cudaEventRecord(evFeats[s], sF);

        k_gemm2<128, 128, 8, 8, true><<<dim3(1, ceildiv(NIMG, 128)), 256, 0, sF>>>(
            feats + s * HDIM, 2 * HDIM, wfa + (size_t)s * HDIM * HIDD, bfa + s * HIDD,
            H1, NIMG, HIDD, HDIM);
        k_gemm<64, 32, 4, 2, false><<<dim3(1, ceildiv(NIMG, 64)), 256, 0, sF>>>(
            H1, HIDD, wfb + (size_t)s * HIDD * CDIM, bfb + s * CDIM, fpred, NIMG, CDIM, HIDD);
        cudaEventRecord(evFpred[s], sF);
        k_kl<<<ceildiv(NIMG, 256), 256, 0, sF>>>(0.025 / ((double)NIMG * (double)CDIM),
                                                 fpred, pred, idxArr);
        cudaEventRecord(evEndF[s], sF);
    }

    // ---- loss pipeline on st0 (overlaps the fusion streams) ----
    k_hist<<<ceildiv(NIMG, 256), 256, 0, st0>>>(img_label, NIMG, gtsimg);
    for (int s = 0; s < NSCALE; s++) {
        int* counts = countsb + (size_t)s * NVOX * CDIM;
        int* gtsvox = gtsvoxb + (size_t)s * CDIM;
        cudaMemsetAsync(counts, 0, (size_t)NVOX * CDIM * sizeof(int), st0);
        cudaMemsetAsync(gtsvox, 0, CDIM * sizeof(int), st0);
        k_scatter<<<ceildiv(NPTS, 256), 256, 0, st0>>>(coors_inv + (size_t)s * NPTS, labels, counts);
        k_argmax<<<ceildiv(NVOX, 256), 256, 0, st0>>>(counts,
            voxlabb + (size_t)s * NVOX, gtsvox);
    }
    // vox seg-losses (gated on pred3d availability)
    for (int s = 0; s < NSCALE; s++) {
        uint32_t* kin = kinb + (size_t)s * CDIM * NVOX;
        uint32_t* kout = koutb + (size_t)s * CDIM * NVOX;
        unsigned char* temp = tempb + (size_t)s * CUBTEMP_BYTES;
        double* cls = clsb + (size_t)s * CDIM;
        cudaStreamWaitEvent(st0, evPred[s], 0);
        k_softmax_keys<<<ceildiv(NVOX, 256), 256, 0, st0>>>(
            predb + (size_t)s * NVOX * CDIM, voxlabb + (size_t)s * NVOX, NVOX, 1.0f, kin);
        sort_lovasz(kin, kout, temp, cls, NVOX, 1.0f, gtsvoxb + (size_t)s * CDIM, st0);
    }
    // fuse seg-losses (gated on fuse_pred availability)
    for (int s = 0; s < NSCALE; s++) {
        uint32_t* kin = kinb + (size_t)s * CDIM * NVOX;
        uint32_t* kout = koutb + (size_t)s * CDIM * NVOX;
        unsigned char* temp = tempb + (size_t)s * CUBTEMP_BYTES;
        double* cls = clsb + (size_t)s * CDIM;
        cudaStreamWaitEvent(st0, evFpred[s], 0);
        k_softmax_keys<<<ceildiv(NIMG, 256), 256, 0, st0>>>(
            fpredb + (size_t)s * NIMG * CDIM, img_label, NIMG, 0.5f, kin);
        sort_lovasz(kin, kout, temp, cls, NIMG, 0.5f, gtsimg, st0);
    }
    // final classifier (needs both scales' feats)
    for (int s = 0; s < NSCALE; s++) cudaStreamWaitEvent(st0, evFeats[s], 0);
    k_gemm2<128, 128, 8, 8, true><<<dim3(1, ceildiv(NIMG, 128)), 256, 0, st0>>>(
        feats, 2 * HDIM, clw1, clb1, HF, NIMG, HIDD, 2 * HDIM);
    k_gemm<64, 32, 4, 2, false><<<dim3(1, ceildiv(NIMG, 64)), 256, 0, st0>>>(
        HF, HIDD, clw2, clb2, fpredF, NIMG, CDIM, HIDD);
    k_softmax_keys<<<ceildiv(NIMG, 256), 256, 0, st0>>>(fpredF, img_label, NIMG, 1.0f, kinF);
    sort_lovasz(kinF, koutF, tempF, clsF, NIMG, 1.0f, gtsimg, st0);

    // join KL tails before reading the loss
    for (int s = 0; s < NSCALE; s++) cudaStreamWaitEvent(st0, evEndF[s], 0);
    k_finish<<<1, 1, 0, st0>>>((float*)d_out);
}

// round 7
// speedup vs baseline: 1.2882x; 1.2882x over previous
#include <cuda_runtime.h>
#include <cub/cub.cuh>
#include <math.h>
#include <stdint.h>

#define NSCALE 2
#define NPTS   240000
#define NVOX   80000
#define NPB    120000
#define MPB    30000
#define HDIM   64
#define CDIM   20
#define MIDD   16
#define HIDD   128
#define NIMG   60000
#define CUBTEMP_BYTES (24u*1024u*1024u)
#define QLEV   262143.0f   // 18-bit linear err quantization
#define NLOSS  5           // vox0, vox1, fuse0, fuse1, final

// ------------------------- static device scratch -------------------------
__device__ float g_H1[NSCALE][(size_t)NVOX * HIDD];
__device__ float g_pred3d[NSCALE][(size_t)NVOX * CDIM];
__device__ int   g_counts[NSCALE][(size_t)NVOX * CDIM];
__device__ int   g_voxlab[NSCALE][NVOX];
__device__ int   g_idx[NSCALE][NIMG];
__device__ float g_P[NSCALE][(size_t)NIMG * HDIM];
__device__ float g_a1[NSCALE][(size_t)NIMG * MIDD];
__device__ float g_a2[NSCALE][(size_t)NIMG * MIDD];
__device__ float g_attw[NSCALE][(size_t)NIMG * 2];
__device__ float g_y1[NSCALE][(size_t)NIMG * HDIM];
__device__ float g_y2[NSCALE][(size_t)NIMG * HDIM];
__device__ float g_fpred[NSCALE][(size_t)NIMG * CDIM];
__device__ float g_stats[NSCALE][4 * HDIM];
// per-loss-instance sort buffers (worst-case CDIM*NVOX each)
__device__ uint32_t g_keys_in[NLOSS][(size_t)CDIM * NVOX];
__device__ uint32_t g_keys_out[NLOSS][(size_t)CDIM * NVOX];
__device__ double g_classLoss[NLOSS][CDIM];
__device__ unsigned char g_cubtemp[2][CUBTEMP_BYTES];   // one per created stream
__device__ int    g_gts_vox[NSCALE][CDIM];
__device__ float g_HF[(size_t)NIMG * HIDD];
__device__ float g_fpredF[(size_t)NIMG * CDIM];
__device__ float g_feats[(size_t)NIMG * 2 * HDIM];   // disjoint column slices per scale
__device__ int    g_gts_img[CDIM];
__device__ double g_loss;

// ------------------------- reduction helper -------------------------
__device__ __forceinline__ double blockReduceSumD(double v) {
    __shared__ double sh[32];
    int lane = threadIdx.x & 31, wid = threadIdx.x >> 5;
#pragma unroll
    for (int o = 16; o > 0; o >>= 1) v += __shfl_down_sync(0xffffffffu, v, o);
    if (lane == 0) sh[wid] = v;
    __syncthreads();
    int nw = (blockDim.x + 31) >> 5;
    v = (threadIdx.x < nw) ? sh[threadIdx.x] : 0.0;
    if (wid == 0) {
#pragma unroll
        for (int o = 16; o > 0; o >>= 1) v += __shfl_down_sync(0xffffffffu, v, o);
    }
    return v;  // valid on thread 0
}

// ------------------------- elementwise kernels -------------------------
__global__ void k_scatter(const int* __restrict__ coors_s, const int* __restrict__ labels,
                          int* __restrict__ counts) {
    int i = blockIdx.x * blockDim.x + threadIdx.x;
    if (i < NPTS) atomicAdd(&counts[(size_t)coors_s[i] * CDIM + labels[i]], 1);
}

__global__ void k_argmax(const int* __restrict__ counts, int* __restrict__ voxlab,
                         int* __restrict__ gts) {
    __shared__ int h[CDIM];
    if (threadIdx.x < CDIM) h[threadIdx.x] = 0;
    __syncthreads();
    int v = blockIdx.x * blockDim.x + threadIdx.x;
    if (v < NVOX) {
        const int* row = counts + (size_t)v * CDIM;
        int best = row[0], bi = 0;
#pragma unroll
        for (int c = 1; c < CDIM; c++) { int x = row[c]; if (x > best) { best = x; bi = c; } }
        voxlab[v] = bi;
        atomicAdd(&h[bi], 1);
    }
    __syncthreads();
    if (threadIdx.x < CDIM && h[threadIdx.x]) atomicAdd(&gts[threadIdx.x], h[threadIdx.x]);
}

__global__ void k_hist(const int* __restrict__ lab, int n, int* __restrict__ gts) {
    __shared__ int h[CDIM];
    if (threadIdx.x < CDIM) h[threadIdx.x] = 0;
    __syncthreads();
    int i = blockIdx.x * blockDim.x + threadIdx.x;
    if (i < n) atomicAdd(&h[lab[i]], 1);
    __syncthreads();
    if (threadIdx.x < CDIM && h[threadIdx.x]) atomicAdd(&gts[threadIdx.x], h[threadIdx.x]);
}

__global__ void k_idxgather(const float* __restrict__ pts_s, const int* __restrict__ coors_s,
                            const int* __restrict__ p2img, int* __restrict__ idxArr,
                            float* __restrict__ P) {
    int t = blockIdx.x * blockDim.x + threadIdx.x;
    if (t < NIMG * HDIM) {
        int r = t >> 6, c = t & 63;
        int b = r / MPB;
        int vi = coors_s[b * NPB + p2img[r]];
        if (c == 0) idxArr[r] = vi;
        P[t] = pts_s[(size_t)vi * HDIM + c];
    }
}

__global__ void k_att(const float* __restrict__ a1, const float* __restrict__ a2,
                      float* __restrict__ attw,
                      const float* __restrict__ fc3w, const float* __restrict__ fc3b) {
    int r = blockIdx.x * blockDim.x + threadIdx.x;
    if (r >= NIMG) return;
    float z0 = fc3b[0], z1 = fc3b[1];
#pragma unroll
    for (int j = 0; j < MIDD; j++) {
        float v = a1[(size_t)r * MIDD + j];
        z0 += v * fc3w[j * 2 + 0];
        z1 += v * fc3w[j * 2 + 1];
    }
#pragma unroll
    for (int j = 0; j < MIDD; j++) {
        float v = a2[(size_t)r * MIDD + j];
        z0 += v * fc3w[(MIDD + j) * 2 + 0];
        z1 += v * fc3w[(MIDD + j) * 2 + 1];
    }
    attw[2 * r + 0] = 1.f / (1.f + expf(-z0));
    attw[2 * r + 1] = 1.f / (1.f + expf(-z1));
}

#define ROWSPB 512
__global__ void k_colstats(const float* __restrict__ y, float* __restrict__ stats, int statsOff) {
    const int col = threadIdx.x & 63;
    const int grp = threadIdx.x >> 6;  // 0..3
    float s = 0.f, q = 0.f;
    int r0 = blockIdx.x * ROWSPB;
    int rend = r0 + ROWSPB; if (rend > NIMG) rend = NIMG;
    for (int r = r0 + grp; r < rend; r += 4) {
        float v = y[(size_t)r * HDIM + col];
        s += v; q += v * v;
    }
    __shared__ float sh[2][4][64];
    sh[0][grp][col] = s; sh[1][grp][col] = q;
    __syncthreads();
    if (grp == 0) {
        s = sh[0][0][col] + sh[0][1][col] + sh[0][2][col] + sh[0][3][col];
        q = sh[1][0][col] + sh[1][1][col] + sh[1][2][col] + sh[1][3][col];
        atomicAdd(&stats[statsOff + col], s);
        atomicAdd(&stats[statsOff + 64 + col], q);
    }
}

__global__ void k_fuse(const float* __restrict__ y1, const float* __restrict__ y2,
                       const float* __restrict__ attw, const float* __restrict__ stats,
                       const float* __restrict__ g1, const float* __restrict__ b1,
                       const float* __restrict__ g2, const float* __restrict__ b2, int s) {
    int t = blockIdx.x * blockDim.x + threadIdx.x;
    if (t >= NIMG * HDIM) return;
    int r = t >> 6, c = t & 63;
    const float n = (float)NIMG;
    float mu1 = stats[c] / n;        float var1 = stats[64 + c] / n - mu1 * mu1;
    float mu2 = stats[128 + c] / n;  float var2 = stats[192 + c] / n - mu2 * mu2;
    float v1 = fmaxf((y1[t] - mu1) * rsqrtf(var1 + 1e-5f) * g1[c] + b1[c], 0.f);
    float v2 = fmaxf((y2[t] - mu2) * rsqrtf(var2 + 1e-5f) * g2[c] + b2[c], 0.f);
    g_feats[(size_t)r * (2 * HDIM) + s * HDIM + c] = v1 * attw[2 * r] + v2 * attw[2 * r + 1];
}

// ------------------------- big GEMM (f32x2) -------------------------
template <int BM, int BN, int TM, int TN, bool RELU>
__global__ void __launch_bounds__(256) k_gemm2(const float* __restrict__ A, int lda,
                                               const float* __restrict__ W,
                                               const float* __restrict__ bias,
                                               float* __restrict__ Cm,
                                               int M, int N, int K) {
    constexpr int TX = BN / TN;
    constexpr int TY = BM / TM;
    static_assert(TX * TY == 256 && TM == 8 && (TN == 4 || TN == 8), "bad tile");
    __shared__ __align__(16) float As[16][BM + 4];
    __shared__ __align__(16) float Ws[16][BN + 4];
    const int bm = blockIdx.y * BM, bn = blockIdx.x * BN;
    const int tid = threadIdx.x;
    const int tx = tid % TX, ty = tid / TX;
    unsigned long long acc[TM][TN / 2] = {};
    for (int k0 = 0; k0 < K; k0 += 16) {
#pragma unroll
        for (int it = 0; it < BM / 64; it++) {
            int g = tid + it * 256;
            int m = g >> 2, q = g & 3;
            int gm = bm + m;
            float4 v = make_float4(0.f, 0.f, 0.f, 0.f);
            if (gm < M) v = *(const float4*)&A[(size_t)gm * lda + k0 + 4 * q];
            As[4 * q + 0][m] = v.x; As[4 * q + 1][m] = v.y;
            As[4 * q + 2][m] = v.z; As[4 * q + 3][m] = v.w;
        }
#pragma unroll
        for (int it = 0; it < BN / 64; it++) {
            int g = tid + it * 256;
            int kk = g / (BN / 4), nq = g % (BN / 4);
            *(float4*)&Ws[kk][4 * nq] = *(const float4*)&W[(size_t)(k0 + kk) * N + bn + 4 * nq];
        }
        __syncthreads();
#pragma unroll
        for (int kk = 0; kk < 16; kk++) {
            float a[TM];
            *(float4*)&a[0] = *(const float4*)&As[kk][ty * TM];
            *(float4*)&a[4] = *(const float4*)&As[kk][ty * TM + 4];
            unsigned long long b2[TN / 2];
            *(ulonglong2*)&b2[0] = *(const ulonglong2*)&Ws[kk][tx * TN];
            if constexpr (TN == 8) {
                *(ulonglong2*)&b2[2] = *(const ulonglong2*)&Ws[kk][tx * TN + 4];
            }
#pragma unroll
            for (int i = 0; i < TM; i++) {
                unsigned long long a2;
                asm("mov.b64 %0, {%1, %1};" : "=l"(a2) : "f"(a[i]));
#pragma unroll
                for (int j = 0; j < TN / 2; j++)
                    asm("fma.rn.f32x2 %0, %1, %2, %0;" : "+l"(acc[i][j]) : "l"(a2), "l"(b2[j]));
            }
        }
        __syncthreads();
    }
#pragma unroll
    for (int i = 0; i < TM; i++) {
        int gm = bm + ty * TM + i;
        if (gm >= M) continue;
#pragma unroll
        for (int j = 0; j < TN / 2; j++) {
            int gn = bn + tx * TN + 2 * j;
            float lo = __uint_as_float((unsigned)(acc[i][j] & 0xFFFFFFFFull)) + bias[gn];
            float hi = __uint_as_float((unsigned)(acc[i][j] >> 32)) + bias[gn + 1];
            if (RELU) { lo = fmaxf(lo, 0.f); hi = fmaxf(hi, 0.f); }
            *(float2*)&Cm[(size_t)gm * N + gn] = make_float2(lo, hi);
        }
    }
}

// ------------------------- small-N GEMM (scalar) -------------------------
template <int BM, int BN, int TM, int TN, bool RELU>
__global__ void __launch_bounds__(256) k_gemm(const float* __restrict__ A, int lda,
                                              const float* __restrict__ W,
                                              const float* __restrict__ bias,
                                              float* __restrict__ Cm,
                                              int M, int N, int K) {
    constexpr int TX = BN / TN;
    constexpr int TY = BM / TM;
    static_assert(TX * TY == 256, "bad tile");
    __shared__ __align__(16) float As[16][BM + 4];
    __shared__ __align__(16) float Ws[16][BN + 4];
    const int bm = blockIdx.y * BM, bn = blockIdx.x * BN;
    const int tid = threadIdx.x;
    const int tx = tid % TX, ty = tid / TX;
    float acc[TM][TN] = {};
    for (int k0 = 0; k0 < K; k0 += 16) {
#pragma unroll
        for (int e = tid; e < BM * 16; e += 256) {
            int m = e >> 4, kk = e & 15;
            int gm = bm + m;
            As[kk][m] = (gm < M) ? A[(size_t)gm * lda + (k0 + kk)] : 0.f;
        }
#pragma unroll
        for (int e = tid; e < BN * 16; e += 256) {
            int kk = e / BN, n2 = e % BN;
            int gn = bn + n2;
            Ws[kk][n2] = (gn < N) ? W[(size_t)(k0 + kk) * N + gn] : 0.f;
        }
        __syncthreads();
#pragma unroll
        for (int kk = 0; kk < 16; kk++) {
            float a[TM], b[TN];
#pragma unroll
            for (int i = 0; i < TM; i++) a[i] = As[kk][ty * TM + i];
#pragma unroll
            for (int j = 0; j < TN; j++) b[j] = Ws[kk][tx * TN + j];
#pragma unroll
            for (int i = 0; i < TM; i++)
#pragma unroll
                for (int j = 0; j < TN; j++) acc[i][j] += a[i] * b[j];
        }
        __syncthreads();
    }
#pragma unroll
    for (int i = 0; i < TM; i++) {
        int gm = bm + ty * TM + i;
        if (gm >= M) continue;
#pragma unroll
        for (int j = 0; j < TN; j++) {
            int gn = bn + tx * TN + j;
            if (gn < N) {
                float v = acc[i][j] + bias[gn];
                if (RELU) v = fmaxf(v, 0.f);
                Cm[(size_t)gm * N + gn] = v;
            }
        }
    }
}

// ------------------------- loss kernels -------------------------
// key = (c << 19) | (q18 << 1) | fg ; q18 = round(err * QLEV)
__global__ void k_softmax_keys(const float* __restrict__ logits, const int* __restrict__ lab,
                               int n, float ce_w, uint32_t* __restrict__ keys) {
    int i = blockIdx.x * blockDim.x + threadIdx.x;
    double ce = 0.0;
    if (i < n) {
        float z[CDIM];
#pragma unroll
        for (int c = 0; c < CDIM; c++) z[c] = logits[(size_t)i * CDIM + c];
        float m = z[0];
#pragma unroll
        for (int c = 1; c < CDIM; c++) m = fmaxf(m, z[c]);
        float se = 0.f;
#pragma unroll
        for (int c = 0; c < CDIM; c++) se += expf(z[c] - m);
        float ls = logf(se);
        int l = lab[i];
        ce = -(double)(z[l] - m - ls);
#pragma unroll
        for (int c = 0; c < CDIM; c++) {
            float p = expf(z[c] - m - ls);
            uint32_t fg = (c == l) ? 1u : 0u;
            float err = fabsf((float)fg - p);
            uint32_t q = (uint32_t)__float2uint_rn(err * QLEV);
            if (q > 262143u) q = 262143u;
            keys[(size_t)c * n + i] = ((uint32_t)c << 19) | (q << 1) | fg;
        }
    }
    double tot = blockReduceSumD(ce);
    if (threadIdx.x == 0) atomicAdd(&g_loss, tot * (double)ce_w / (double)n);
}

// one block per class; iterate descending err over the ascending-sorted segment
__global__ void __launch_bounds__(1024) k_lovasz(const uint32_t* __restrict__ keysAll,
                                                 const int* __restrict__ gts,
                                                 double* __restrict__ classLoss, int n) {
    int c = blockIdx.x;
    int tid = threadIdx.x, lane = tid & 31, wid = tid >> 5;
    const uint32_t* keys = keysAll + (size_t)c * n;
    float g = (float)gts[c];
    __shared__ int shWs[32];
    __shared__ double shD[32];
    int carry = 0;
    double acc = 0.0;
    for (int pos0 = 0; pos0 < n; pos0 += 1024) {
        int pos = pos0 + tid;
        int f = 0; float e = 0.f;
        if (pos < n) {
            uint32_t k = keys[n - 1 - pos];   // descending err
            f = (int)(k & 1u);
            e = (float)((k >> 1) & 0x3FFFFu) * (1.0f / QLEV);
        }
        unsigned bal = __ballot_sync(0xffffffffu, f);
        int inclw = __popc(bal & (0xFFFFFFFFu >> (31 - lane)));
        if (lane == 31) shWs[wid] = inclw;
        __syncthreads();
        if (wid == 0) {
            int v = shWs[lane];
#pragma unroll
            for (int o = 1; o < 32; o <<= 1) {
                int u = __shfl_up_sync(0xffffffffu, v, o);
                if (lane >= o) v += u;
            }
            shWs[lane] = v;
        }
        __syncthreads();
        int cf = carry + inclw + (wid > 0 ? shWs[wid - 1] : 0);
        int total = shWs[31];
        if (pos < n) {
            float fi = (float)pos + 1.f;
            float cff = (float)cf;
            float jac = 1.f - (g - cff) / (g + fi - cff);
            float jacp = 0.f;
            if (pos > 0) {
                float cfp = cff - (float)f;
                jacp = 1.f - (g - cfp) / (g + (fi - 1.f) - cfp);
            }
            acc += (double)(e * (jac - jacp));
        }
        carry += total;
        __syncthreads();
    }
#pragma unroll
    for (int o = 16; o > 0; o >>= 1) acc += __shfl_down_sync(0xffffffffu, acc, o);
    if (lane == 0) shD[wid] = acc;
    __syncthreads();
    if (wid == 0) {
        double v = shD[lane];
#pragma unroll
        for (int o = 16; o > 0; o >>= 1) v += __shfl_down_sync(0xffffffffu, v, o);
        if (tid == 0) classLoss[c] = v;
    }
}

__global__ void k_lovreduce(float w, const int* __restrict__ gts,
                            const double* __restrict__ classLoss) {
    int tid = threadIdx.x;
    double s = 0.0; int pc = 0;
    if (tid < CDIM && gts[tid] > 0) { s = classLoss[tid]; pc = 1; }
#pragma unroll
    for (int o = 16; o > 0; o >>= 1) {
        s += __shfl_down_sync(0xffffffffu, s, o);
        pc += __shfl_down_sync(0xffffffffu, pc, o);
    }
    if (tid == 0) {
        int d = pc > 0 ? pc : 1;
        atomicAdd(&g_loss, (double)w * s / (double)d);
    }
}

__global__ void k_kl(double w, const float* __restrict__ fpred,
                     const float* __restrict__ pred3d, const int* __restrict__ idxArr) {
    int r = blockIdx.x * blockDim.x + threadIdx.x;
    double local = 0.0;
    if (r < NIMG) {
        float zf[CDIM], zp[CDIM];
        int vi = idxArr[r];
#pragma unroll
        for (int c = 0; c < CDIM; c++) {
            zf[c] = fpred[(size_t)r * CDIM + c];
            zp[c] = pred3d[(size_t)vi * CDIM + c];
        }
        float mf = zf[0], mp = zp[0];
#pragma unroll
        for (int c = 1; c < CDIM; c++) { mf = fmaxf(mf, zf[c]); mp = fmaxf(mp, zp[c]); }
        float sf = 0.f, sp = 0.f;
#pragma unroll
        for (int c = 0; c < CDIM; c++) { sf += expf(zf[c] - mf); sp += expf(zp[c] - mp); }
        float lsf = logf(sf), lsp = logf(sp);
        float acc = 0.f;
#pragma unroll
        for (int c = 0; c < CDIM; c++) {
            float lp = zf[c] - mf - lsf;
            float p = expf(lp);
            float lq = zp[c] - mp - lsp;
            acc += p * (lp - lq);
        }
        local = (double)acc;
    }
    double tot = blockReduceSumD(local);
    if (threadIdx.x == 0) atomicAdd(&g_loss, tot * w);
}

__global__ void k_finish(float* out) { out[0] = (float)g_loss; }

// ------------------------- host -------------------------
static inline int ceildiv(int a, int b) { return (a + b - 1) / b; }

extern "C" void kernel_launch(void* const* d_in, const int* in_sizes, int n_in,
                              void* d_out, int out_size) {
    const float* img_feat = (const float*)d_in[0];
    const float* pts_feat = (const float*)d_in[1];
    const int*   coors_inv = (const int*)d_in[2];
    const int*   labels   = (const int*)d_in[3];
    const int*   img_label = (const int*)d_in[4];
    const int*   p2img    = (const int*)d_in[5];
    const float* w3a = (const float*)d_in[6];  const float* b3a = (const float*)d_in[7];
    const float* w3b = (const float*)d_in[8];  const float* b3b = (const float*)d_in[9];
    const float* wfa = (const float*)d_in[10]; const float* bfa = (const float*)d_in[11];
    const float* wfb = (const float*)d_in[12]; const float* bfb = (const float*)d_in[13];
    const float* fc1w = (const float*)d_in[14]; const float* fc1b = (const float*)d_in[15];
    const float* fc2w = (const float*)d_in[16]; const float* fc2b = (const float*)d_in[17];
    const float* fc3w = (const float*)d_in[18]; const float* fc3b = (const float*)d_in[19];
    const float* c1w = (const float*)d_in[20]; const float* c1b = (const float*)d_in[21];
    const float* bn1g = (const float*)d_in[22]; const float* bn1b = (const float*)d_in[23];
    const float* c2w = (const float*)d_in[24]; const float* c2b = (const float*)d_in[25];
    const float* bn2g = (const float*)d_in[26]; const float* bn2b = (const float*)d_in[27];
    const float* clw1 = (const float*)d_in[28]; const float* clb1 = (const float*)d_in[29];
    const float* clw2 = (const float*)d_in[30]; const float* clb2 = (const float*)d_in[31];

    void *pv;
    cudaGetSymbolAddress(&pv, g_H1);       float* H1b = (float*)pv;
    cudaGetSymbolAddress(&pv, g_pred3d);   float* predb = (float*)pv;
    cudaGetSymbolAddress(&pv, g_counts);   int* countsb = (int*)pv;
    cudaGetSymbolAddress(&pv, g_voxlab);   int* voxlabb = (int*)pv;
    cudaGetSymbolAddress(&pv, g_idx);      int* idxb = (int*)pv;
    cudaGetSymbolAddress(&pv, g_P);        float* Pb = (float*)pv;
    cudaGetSymbolAddress(&pv, g_a1);       float* a1b = (float*)pv;
    cudaGetSymbolAddress(&pv, g_a2);       float* a2b = (float*)pv;
    cudaGetSymbolAddress(&pv, g_attw);     float* attwb = (float*)pv;
    cudaGetSymbolAddress(&pv, g_y1);       float* y1b = (float*)pv;
    cudaGetSymbolAddress(&pv, g_y2);       float* y2b = (float*)pv;
    cudaGetSymbolAddress(&pv, g_fpred);    float* fpredb = (float*)pv;
    cudaGetSymbolAddress(&pv, g_stats);    float* statsb = (float*)pv;
    cudaGetSymbolAddress(&pv, g_keys_in);  uint32_t* kinb = (uint32_t*)pv;
    cudaGetSymbolAddress(&pv, g_keys_out); uint32_t* koutb = (uint32_t*)pv;
    cudaGetSymbolAddress(&pv, g_classLoss);double* clsb = (double*)pv;
    cudaGetSymbolAddress(&pv, g_cubtemp);  unsigned char* tempb = (unsigned char*)pv;
    cudaGetSymbolAddress(&pv, g_gts_vox);  int* gtsvoxb = (int*)pv;
    cudaGetSymbolAddress(&pv, g_HF);       float* HF = (float*)pv;
    cudaGetSymbolAddress(&pv, g_fpredF);   float* fpredF = (float*)pv;
    cudaGetSymbolAddress(&pv, g_feats);    float* feats = (float*)pv;
    cudaGetSymbolAddress(&pv, g_gts_img);  int* gtsimg = (int*)pv;
    cudaGetSymbolAddress(&pv, g_loss);     void* p_loss = pv;

    // streams/events: 2 created streams (same width as last passing runs)
    static cudaStream_t strS[NSCALE] = {};
    static cudaEvent_t evFork = nullptr;
    static cudaEvent_t evPred[NSCALE] = {}, evFpred[NSCALE] = {}, evFeats[NSCALE] = {};
    static cudaEvent_t evEnd[NSCALE] = {};
    if (!strS[0]) {
        for (int s = 0; s < NSCALE; s++) {
            cudaStreamCreateWithFlags(&strS[s], cudaStreamNonBlocking);
            cudaEventCreateWithFlags(&evPred[s], cudaEventDisableTiming);
            cudaEventCreateWithFlags(&evFpred[s], cudaEventDisableTiming);
            cudaEventCreateWithFlags(&evFeats[s], cudaEventDisableTiming);
            cudaEventCreateWithFlags(&evEnd[s], cudaEventDisableTiming);
        }
        cudaEventCreateWithFlags(&evFork, cudaEventDisableTiming);
    }

    cudaStream_t st0 = 0;
    // tiny pre-fork setup on legacy stream (runs before everything anyway)
    cudaMemsetAsync(p_loss, 0, sizeof(double), st0);
    cudaMemsetAsync(gtsimg, 0, CDIM * sizeof(int), st0);
    cudaMemsetAsync(countsb, 0, (size_t)NSCALE * NVOX * CDIM * sizeof(int), st0);
    cudaMemsetAsync(gtsvoxb, 0, NSCALE * CDIM * sizeof(int), st0);
    k_hist<<<ceildiv(NIMG, 256), 256, 0, st0>>>(img_label, NIMG, gtsimg);
    cudaEventRecord(evFork, st0);
    for (int s = 0; s < NSCALE; s++) cudaStreamWaitEvent(strS[s], evFork, 0);

    // loss-instance buffers: 0=vox0, 1=vox1, 2=fuse0, 3=fuse1, 4=final
    auto kin  = [&](int i) { return kinb  + (size_t)i * CDIM * NVOX; };
    auto kout = [&](int i) { return koutb + (size_t)i * CDIM * NVOX; };
    auto cls  = [&](int i) { return clsb + (size_t)i * CDIM; };
    auto sort_lovasz = [&](int li, int n, float weight, const int* gts,
                           int tempIdx, cudaStream_t st) {
        size_t tb = CUBTEMP_BYTES;
        cub::DeviceRadixSort::SortKeys(tempb + (size_t)tempIdx * CUBTEMP_BYTES, tb,
                                       kin(li), kout(li), CDIM * n, 0, 24, st);
        k_lovasz<<<CDIM, 1024, 0, st>>>(kout(li), gts, cls(li), n);
        k_lovreduce<<<1, 32, 0, st>>>(weight, gts, cls(li));
    };

    // ---- fusion chains (one per created stream) ----
    for (int s = 0; s < NSCALE; s++) {
        cudaStream_t sF = strS[s];
        const float* pts_s = pts_feat + (size_t)s * NVOX * HDIM;
        const float* img_s = img_feat + (size_t)s * NIMG * HDIM;
        const int* coors_s = coors_inv + (size_t)s * NPTS;
        float* H1 = H1b + (size_t)s * NVOX * HIDD;
        float* pred = predb + (size_t)s * NVOX * CDIM;
        int* idxArr = idxb + (size_t)s * NIMG;
        float* P = Pb + (size_t)s * NIMG * HDIM;
        float* a1 = a1b + (size_t)s * NIMG * MIDD;
        float* a2 = a2b + (size_t)s * NIMG * MIDD;
        float* attw = attwb + (size_t)s * NIMG * 2;
        float* y1 = y1b + (size_t)s * NIMG * HDIM;
        float* y2 = y2b + (size_t)s * NIMG * HDIM;
        float* fpred = fpredb + (size_t)s * NIMG * CDIM;
        float* stats = statsb + (size_t)s * 4 * HDIM;

        k_gemm2<128, 128, 8, 8, true><<<dim3(1, ceildiv(NVOX, 128)), 256, 0, sF>>>(
            pts_s, HDIM, w3a + (size_t)s * HDIM * HIDD, b3a + s * HIDD, H1, NVOX, HIDD, HDIM);
        k_gemm<64, 32, 4, 2, false><<<dim3(1, ceildiv(NVOX, 64)), 256, 0, sF>>>(
            H1, HIDD, w3b + (size_t)s * HIDD * CDIM, b3b + s * CDIM, pred, NVOX, CDIM, HIDD);
        cudaEventRecord(evPred[s], sF);

        k_idxgather<<<ceildiv(NIMG * HDIM, 256), 256, 0, sF>>>(pts_s, coors_s, p2img, idxArr, P);
        k_gemm<64, 32, 4, 2, false><<<dim3(1, ceildiv(NIMG, 64)), 256, 0, sF>>>(
            P, HDIM, fc1w + (size_t)s * HDIM * MIDD, fc1b + s * MIDD, a1, NIMG, MIDD, HDIM);
        k_gemm<64, 32, 4, 2, false><<<dim3(1, ceildiv(NIMG, 64)), 256, 0, sF>>>(
            img_s, HDIM, fc2w + (size_t)s * HDIM * MIDD, fc2b + s * MIDD, a2, NIMG, MIDD, HDIM);
        k_att<<<ceildiv(NIMG, 256), 256, 0, sF>>>(a1, a2, attw,
            fc3w + (size_t)s * 2 * MIDD * 2, fc3b + s * 2);
        k_gemm2<128, 64, 8, 4, false><<<dim3(1, ceildiv(NIMG, 128)), 256, 0, sF>>>(
            P, HDIM, c1w + (size_t)s * HDIM * HDIM, c1b + s * HDIM, y1, NIMG, HDIM, HDIM);
        k_gemm2<128, 64, 8, 4, false><<<dim3(1, ceildiv(NIMG, 128)), 256, 0, sF>>>(
            img_s, HDIM, c2w + (size_t)s * HDIM * HDIM, c2b + s * HDIM, y2, NIMG, HDIM, HDIM);
        cudaMemsetAsync(stats, 0, 4 * HDIM * sizeof(float), sF);
        k_colstats<<<ceildiv(NIMG, ROWSPB), 256, 0, sF>>>(y1, stats, 0);
        k_colstats<<<ceildiv(NIMG, ROWSPB), 256, 0, sF>>>(y2, stats, 128);
        k_fuse<<<ceildiv(NIMG * HDIM, 256), 256, 0, sF>>>(y1, y2, attw, stats,
            bn1g + s * HDIM, bn1b + s * HDIM, bn2g + s * HDIM, bn2b + s * HDIM, s);
        cudaEventRecord(evFeats[s], sF);

        k_gemm2<128, 128, 8, 8, true><<<dim3(1, ceildiv(NIMG, 128)), 256, 0, sF>>>(
            feats + s * HDIM, 2 * HDIM, wfa + (size_t)s * HDIM * HIDD, bfa + s * HIDD,
            H1, NIMG, HIDD, HDIM);
        k_gemm<64, 32, 4, 2, false><<<dim3(1, ceildiv(NIMG, 64)), 256, 0, sF>>>(
            H1, HIDD, wfb + (size_t)s * HIDD * CDIM, bfb + s * CDIM, fpred, NIMG, CDIM, HIDD);
        cudaEventRecord(evFpred[s], sF);
        k_kl<<<ceildiv(NIMG, 256), 256, 0, sF>>>(0.025 / ((double)NIMG * (double)CDIM),
                                                 fpred, pred, idxArr);
    }

    // ---- loss tails (cross-assigned to the opposite stream) ----
    // stream 0 tail: vox-loss for scale 1 + final classifier chain
    {
        cudaStream_t st = strS[0];
        int other = 1;
        k_scatter<<<ceildiv(NPTS, 256), 256, 0, st>>>(
            coors_inv + (size_t)other * NPTS, labels, countsb + (size_t)other * NVOX * CDIM);
        k_argmax<<<ceildiv(NVOX, 256), 256, 0, st>>>(
            countsb + (size_t)other * NVOX * CDIM, voxlabb + (size_t)other * NVOX,
            gtsvoxb + (size_t)other * CDIM);
        cudaStreamWaitEvent(st, evPred[other], 0);
        k_softmax_keys<<<ceildiv(NVOX, 256), 256, 0, st>>>(
            predb + (size_t)other * NVOX * CDIM, voxlabb + (size_t)other * NVOX,
            NVOX, 1.0f, kin(1));
        sort_lovasz(1, NVOX, 1.0f, gtsvoxb + (size_t)other * CDIM, 0, st);

        cudaStreamWaitEvent(st, evFeats[1], 0);   // feats slice 0 is in-stream
        k_gemm2<128, 128, 8, 8, true><<<dim3(1, ceildiv(NIMG, 128)), 256, 0, st>>>(
            feats, 2 * HDIM, clw1, clb1, HF, NIMG, HIDD, 2 * HDIM);
        k_gemm<64, 32, 4, 2, false><<<dim3(1, ceildiv(NIMG, 64)), 256, 0, st>>>(
            HF, HIDD, clw2, clb2, fpredF, NIMG, CDIM, HIDD);
        k_softmax_keys<<<ceildiv(NIMG, 256), 256, 0, st>>>(fpredF, img_label, NIMG, 1.0f, kin(4));
        sort_lovasz(4, NIMG, 1.0f, gtsimg, 0, st);
        cudaEventRecord(evEnd[0], st);
    }
    // stream 1 tail: vox-loss scale 0 + both fuse losses
    {
        cudaStream_t st = strS[1];
        int other = 0;
        k_scatter<<<ceildiv(NPTS, 256), 256, 0, st>>>(
            coors_inv + (size_t)other * NPTS, labels, countsb + (size_t)other * NVOX * CDIM);
        k_argmax<<<ceildiv(NVOX, 256), 256, 0, st>>>(
            countsb + (size_t)other * NVOX * CDIM, voxlabb + (size_t)other * NVOX,
            gtsvoxb + (size_t)other * CDIM);
        cudaStreamWaitEvent(st, evPred[other], 0);
        k_softmax_keys<<<ceildiv(NVOX, 256), 256, 0, st>>>(
            predb + (size_t)other * NVOX * CDIM, voxlabb + (size_t)other * NVOX,
            NVOX, 1.0f, kin(0));
        sort_lovasz(0, NVOX, 1.0f, gtsvoxb + (size_t)other * CDIM, 1, st);

        cudaStreamWaitEvent(st, evFpred[0], 0);
        k_softmax_keys<<<ceildiv(NIMG, 256), 256, 0, st>>>(
            fpredb, img_label, NIMG, 0.5f, kin(2));
        sort_lovasz(2, NIMG, 0.5f, gtsimg, 1, st);
        // fuse loss scale 1 (fpred1 produced on... stream 1 itself)
        k_softmax_keys<<<ceildiv(NIMG, 256), 256, 0, st>>>(
            fpredb + (size_t)1 * NIMG * CDIM, img_label, NIMG, 0.5f, kin(3));
        sort_lovasz(3, NIMG, 0.5f, gtsimg, 1, st);
        cudaEventRecord(evEnd[1], st);
    }

    // join on legacy stream, emit loss
    for (int s = 0; s < NSCALE; s++) cudaStreamWaitEvent(st0, evEnd[s], 0);
    k_finish<<<1, 1, 0, st0>>>((float*)d_out);
}

// round 8
// speedup vs baseline: 1.9372x; 1.5038x over previous
#include <cuda_runtime.h>
#include <math.h>
#include <stdint.h>

#define NSCALE 2
#define NPTS   240000
#define NVOX   80000
#define NPB    120000
#define MPB    30000
#define HDIM   64
#define CDIM   20
#define MIDD   16
#define HIDD   128
#define NIMG   60000
#define NLOSS  5           // vox0, vox1, fuse0, fuse1, final
#define NB     65536       // 16-bit err quantization bins
#define QL     65535.0f

// ------------------------- static device scratch -------------------------
__device__ float g_H1[NSCALE][(size_t)NVOX * HIDD];
__device__ float g_pred3d[NSCALE][(size_t)NVOX * CDIM];
__device__ int   g_counts[NSCALE][(size_t)NVOX * CDIM];
__device__ int   g_voxlab[NSCALE][NVOX];
__device__ int   g_idx[NSCALE][NIMG];
__device__ float g_P[NSCALE][(size_t)NIMG * HDIM];
__device__ float g_a1[NSCALE][(size_t)NIMG * MIDD];
__device__ float g_a2[NSCALE][(size_t)NIMG * MIDD];
__device__ float g_attw[NSCALE][(size_t)NIMG * 2];
__device__ float g_y1[NSCALE][(size_t)NIMG * HDIM];
__device__ float g_y2[NSCALE][(size_t)NIMG * HDIM];
__device__ float g_fpred[NSCALE][(size_t)NIMG * CDIM];
__device__ float g_stats[NSCALE][4 * HDIM];
// lovasz histograms: packed (n<<32)|f per (class, bin)
__device__ unsigned long long g_hist[NLOSS][(size_t)CDIM * NB];
__device__ unsigned long long g_part[NLOSS][CDIM * 64];
__device__ double g_classLoss[NLOSS][CDIM];
__device__ int    g_gts_vox[NSCALE][CDIM];
__device__ float g_HF[(size_t)NIMG * HIDD];
__device__ float g_fpredF[(size_t)NIMG * CDIM];
__device__ float g_feats[(size_t)NIMG * 2 * HDIM];   // disjoint column slices per scale
__device__ int    g_gts_img[CDIM];
__device__ double g_loss;

// ------------------------- reduction helper -------------------------
__device__ __forceinline__ double blockReduceSumD(double v) {
    __shared__ double sh[32];
    int lane = threadIdx.x & 31, wid = threadIdx.x >> 5;
#pragma unroll
    for (int o = 16; o > 0; o >>= 1) v += __shfl_down_sync(0xffffffffu, v, o);
    if (lane == 0) sh[wid] = v;
    __syncthreads();
    int nw = (blockDim.x + 31) >> 5;
    v = (threadIdx.x < nw) ? sh[threadIdx.x] : 0.0;
    if (wid == 0) {
#pragma unroll
        for (int o = 16; o > 0; o >>= 1) v += __shfl_down_sync(0xffffffffu, v, o);
    }
    return v;  // valid on thread 0
}

// ------------------------- elementwise kernels -------------------------
__global__ void k_scatter(const int* __restrict__ coors_s, const int* __restrict__ labels,
                          int* __restrict__ counts) {
    int i = blockIdx.x * blockDim.x + threadIdx.x;
    if (i < NPTS) atomicAdd(&counts[(size_t)coors_s[i] * CDIM + labels[i]], 1);
}

__global__ void k_argmax(const int* __restrict__ counts, int* __restrict__ voxlab,
                         int* __restrict__ gts) {
    __shared__ int h[CDIM];
    if (threadIdx.x < CDIM) h[threadIdx.x] = 0;
    __syncthreads();
    int v = blockIdx.x * blockDim.x + threadIdx.x;
    if (v < NVOX) {
        const int* row = counts + (size_t)v * CDIM;
        int best = row[0], bi = 0;
#pragma unroll
        for (int c = 1; c < CDIM; c++) { int x = row[c]; if (x > best) { best = x; bi = c; } }
        voxlab[v] = bi;
        atomicAdd(&h[bi], 1);
    }
    __syncthreads();
    if (threadIdx.x < CDIM && h[threadIdx.x]) atomicAdd(&gts[threadIdx.x], h[threadIdx.x]);
}

__global__ void k_hist(const int* __restrict__ lab, int n, int* __restrict__ gts) {
    __shared__ int h[CDIM];
    if (threadIdx.x < CDIM) h[threadIdx.x] = 0;
    __syncthreads();
    int i = blockIdx.x * blockDim.x + threadIdx.x;
    if (i < n) atomicAdd(&h[lab[i]], 1);
    __syncthreads();
    if (threadIdx.x < CDIM && h[threadIdx.x]) atomicAdd(&gts[threadIdx.x], h[threadIdx.x]);
}

__global__ void k_idxgather(const float* __restrict__ pts_s, const int* __restrict__ coors_s,
                            const int* __restrict__ p2img, int* __restrict__ idxArr,
                            float* __restrict__ P) {
    int t = blockIdx.x * blockDim.x + threadIdx.x;
    if (t < NIMG * HDIM) {
        int r = t >> 6, c = t & 63;
        int b = r / MPB;
        int vi = coors_s[b * NPB + p2img[r]];
        if (c == 0) idxArr[r] = vi;
        P[t] = pts_s[(size_t)vi * HDIM + c];
    }
}

__global__ void k_att(const float* __restrict__ a1, const float* __restrict__ a2,
                      float* __restrict__ attw,
                      const float* __restrict__ fc3w, const float* __restrict__ fc3b) {
    int r = blockIdx.x * blockDim.x + threadIdx.x;
    if (r >= NIMG) return;
    float z0 = fc3b[0], z1 = fc3b[1];
#pragma unroll
    for (int j = 0; j < MIDD; j++) {
        float v = a1[(size_t)r * MIDD + j];
        z0 += v * fc3w[j * 2 + 0];
        z1 += v * fc3w[j * 2 + 1];
    }
#pragma unroll
    for (int j = 0; j < MIDD; j++) {
        float v = a2[(size_t)r * MIDD + j];
        z0 += v * fc3w[(MIDD + j) * 2 + 0];
        z1 += v * fc3w[(MIDD + j) * 2 + 1];
    }
    attw[2 * r + 0] = 1.f / (1.f + expf(-z0));
    attw[2 * r + 1] = 1.f / (1.f + expf(-z1));
}

#define ROWSPB 512
__global__ void k_colstats(const float* __restrict__ y, float* __restrict__ stats, int statsOff) {
    const int col = threadIdx.x & 63;
    const int grp = threadIdx.x >> 6;  // 0..3
    float s = 0.f, q = 0.f;
    int r0 = blockIdx.x * ROWSPB;
    int rend = r0 + ROWSPB; if (rend > NIMG) rend = NIMG;
    for (int r = r0 + grp; r < rend; r += 4) {
        float v = y[(size_t)r * HDIM + col];
        s += v; q += v * v;
    }
    __shared__ float sh[2][4][64];
    sh[0][grp][col] = s; sh[1][grp][col] = q;
    __syncthreads();
    if (grp == 0) {
        s = sh[0][0][col] + sh[0][1][col] + sh[0][2][col] + sh[0][3][col];
        q = sh[1][0][col] + sh[1][1][col] + sh[1][2][col] + sh[1][3][col];
        atomicAdd(&stats[statsOff + col], s);
        atomicAdd(&stats[statsOff + 64 + col], q);
    }
}

__global__ void k_fuse(const float* __restrict__ y1, const float* __restrict__ y2,
                       const float* __restrict__ attw, const float* __restrict__ stats,
                       const float* __restrict__ g1, const float* __restrict__ b1,
                       const float* __restrict__ g2, const float* __restrict__ b2, int s) {
    int t = blockIdx.x * blockDim.x + threadIdx.x;
    if (t >= NIMG * HDIM) return;
    int r = t >> 6, c = t & 63;
    const float n = (float)NIMG;
    float mu1 = stats[c] / n;        float var1 = stats[64 + c] / n - mu1 * mu1;
    float mu2 = stats[128 + c] / n;  float var2 = stats[192 + c] / n - mu2 * mu2;
    float v1 = fmaxf((y1[t] - mu1) * rsqrtf(var1 + 1e-5f) * g1[c] + b1[c], 0.f);
    float v2 = fmaxf((y2[t] - mu2) * rsqrtf(var2 + 1e-5f) * g2[c] + b2[c], 0.f);
    g_feats[(size_t)r * (2 * HDIM) + s * HDIM + c] = v1 * attw[2 * r] + v2 * attw[2 * r + 1];
}

// ------------------------- big GEMM (f32x2) -------------------------
template <int BM, int BN, int TM, int TN, bool RELU>
__global__ void __launch_bounds__(256) k_gemm2(const float* __restrict__ A, int lda,
                                               const float* __restrict__ W,
                                               const float* __restrict__ bias,
                                               float* __restrict__ Cm,
                                               int M, int N, int K) {
    constexpr int TX = BN / TN;
    constexpr int TY = BM / TM;
    static_assert(TX * TY == 256 && TM == 8 && (TN == 4 || TN == 8), "bad tile");
    __shared__ __align__(16) float As[16][BM + 4];
    __shared__ __align__(16) float Ws[16][BN + 4];
    const int bm = blockIdx.y * BM, bn = blockIdx.x * BN;
    const int tid = threadIdx.x;
    const int tx = tid % TX, ty = tid / TX;
    unsigned long long acc[TM][TN / 2] = {};
    for (int k0 = 0; k0 < K; k0 += 16) {
#pragma unroll
        for (int it = 0; it < BM / 64; it++) {
            int g = tid + it * 256;
            int m = g >> 2, q = g & 3;
            int gm = bm + m;
            float4 v = make_float4(0.f, 0.f, 0.f, 0.f);
            if (gm < M) v = *(const float4*)&A[(size_t)gm * lda + k0 + 4 * q];
            As[4 * q + 0][m] = v.x; As[4 * q + 1][m] = v.y;
            As[4 * q + 2][m] = v.z; As[4 * q + 3][m] = v.w;
        }
#pragma unroll
        for (int it = 0; it < BN / 64; it++) {
            int g = tid + it * 256;
            int kk = g / (BN / 4), nq = g % (BN / 4);
            *(float4*)&Ws[kk][4 * nq] = *(const float4*)&W[(size_t)(k0 + kk) * N + bn + 4 * nq];
        }
        __syncthreads();
#pragma unroll
        for (int kk = 0; kk < 16; kk++) {
            float a[TM];
            *(float4*)&a[0] = *(const float4*)&As[kk][ty * TM];
            *(float4*)&a[4] = *(const float4*)&As[kk][ty * TM + 4];
            unsigned long long b2[TN / 2];
            *(ulonglong2*)&b2[0] = *(const ulonglong2*)&Ws[kk][tx * TN];
            if constexpr (TN == 8) {
                *(ulonglong2*)&b2[2] = *(const ulonglong2*)&Ws[kk][tx * TN + 4];
            }
#pragma unroll
            for (int i = 0; i < TM; i++) {
                unsigned long long a2;
                asm("mov.b64 %0, {%1, %1};" : "=l"(a2) : "f"(a[i]));
#pragma unroll
                for (int j = 0; j < TN / 2; j++)
                    asm("fma.rn.f32x2 %0, %1, %2, %0;" : "+l"(acc[i][j]) : "l"(a2), "l"(b2[j]));
            }
        }
        __syncthreads();
    }
#pragma unroll
    for (int i = 0; i < TM; i++) {
        int gm = bm + ty * TM + i;
        if (gm >= M) continue;
#pragma unroll
        for (int j = 0; j < TN / 2; j++) {
            int gn = bn + tx * TN + 2 * j;
            float lo = __uint_as_float((unsigned)(acc[i][j] & 0xFFFFFFFFull)) + bias[gn];
            float hi = __uint_as_float((unsigned)(acc[i][j] >> 32)) + bias[gn + 1];
            if (RELU) { lo = fmaxf(lo, 0.f); hi = fmaxf(hi, 0.f); }
            *(float2*)&Cm[(size_t)gm * N + gn] = make_float2(lo, hi);
        }
    }
}

// ------------------------- small-N GEMM (scalar) -------------------------
template <int BM, int BN, int TM, int TN, bool RELU>
__global__ void __launch_bounds__(256) k_gemm(const float* __restrict__ A, int lda,
                                              const float* __restrict__ W,
                                              const float* __restrict__ bias,
                                              float* __restrict__ Cm,
                                              int M, int N, int K) {
    constexpr int TX = BN / TN;
    constexpr int TY = BM / TM;
    static_assert(TX * TY == 256, "bad tile");
    __shared__ __align__(16) float As[16][BM + 4];
    __shared__ __align__(16) float Ws[16][BN + 4];
    const int bm = blockIdx.y * BM, bn = blockIdx.x * BN;
    const int tid = threadIdx.x;
    const int tx = tid % TX, ty = tid / TX;
    float acc[TM][TN] = {};
    for (int k0 = 0; k0 < K; k0 += 16) {
#pragma unroll
        for (int e = tid; e < BM * 16; e += 256) {
            int m = e >> 4, kk = e & 15;
            int gm = bm + m;
            As[kk][m] = (gm < M) ? A[(size_t)gm * lda + (k0 + kk)] : 0.f;
        }
#pragma unroll
        for (int e = tid; e < BN * 16; e += 256) {
            int kk = e / BN, n2 = e % BN;
            int gn = bn + n2;
            Ws[kk][n2] = (gn < N) ? W[(size_t)(k0 + kk) * N + gn] : 0.f;
        }
        __syncthreads();
#pragma unroll
        for (int kk = 0; kk < 16; kk++) {
            float a[TM], b[TN];
#pragma unroll
            for (int i = 0; i < TM; i++) a[i] = As[kk][ty * TM + i];
#pragma unroll
            for (int j = 0; j < TN; j++) b[j] = Ws[kk][tx * TN + j];
#pragma unroll
            for (int i = 0; i < TM; i++)
#pragma unroll
                for (int j = 0; j < TN; j++) acc[i][j] += a[i] * b[j];
        }
        __syncthreads();
    }
#pragma unroll
    for (int i = 0; i < TM; i++) {
        int gm = bm + ty * TM + i;
        if (gm >= M) continue;
#pragma unroll
        for (int j = 0; j < TN; j++) {
            int gn = bn + tx * TN + j;
            if (gn < N) {
                float v = acc[i][j] + bias[gn];
                if (RELU) v = fmaxf(v, 0.f);
                Cm[(size_t)gm * N + gn] = v;
            }
        }
    }
}

// ------------------------- loss kernels -------------------------
// softmax + CE + err-histogram: hist[c*NB + q] += (n=1)<<32 | fg
__global__ void k_softmax_hist(const float* __restrict__ logits, const int* __restrict__ lab,
                               int n, float ce_w, unsigned long long* __restrict__ hist) {
    int i = blockIdx.x * blockDim.x + threadIdx.x;
    double ce = 0.0;
    if (i < n) {
        float z[CDIM];
#pragma unroll
        for (int c = 0; c < CDIM; c++) z[c] = logits[(size_t)i * CDIM + c];
        float m = z[0];
#pragma unroll
        for (int c = 1; c < CDIM; c++) m = fmaxf(m, z[c]);
        float se = 0.f;
#pragma unroll
        for (int c = 0; c < CDIM; c++) se += expf(z[c] - m);
        float ls = logf(se);
        int l = lab[i];
        ce = -(double)(z[l] - m - ls);
#pragma unroll
        for (int c = 0; c < CDIM; c++) {
            float p = expf(z[c] - m - ls);
            unsigned long long fg = (c == l) ? 1ull : 0ull;
            float err = fabsf((float)(c == l) - p);
            uint32_t q = (uint32_t)__float2uint_rn(err * QL);
            if (q > 65535u) q = 65535u;
            atomicAdd(&hist[(size_t)c * NB + q], (1ull << 32) | fg);
        }
    }
    double tot = blockReduceSumD(ce);
    if (threadIdx.x == 0) atomicAdd(&g_loss, tot * (double)ce_w / (double)n);
}

// per-chunk (1024 bins) packed partial sums; grid = CDIM*64, block 256
__global__ void k_lovpart(const unsigned long long* __restrict__ hist,
                          unsigned long long* __restrict__ part) {
    int c = blockIdx.x >> 6, chunk = blockIdx.x & 63;
    const unsigned long long* h = hist + (size_t)c * NB + chunk * 1024;
    int t = threadIdx.x;
    unsigned long long s = 0;
#pragma unroll
    for (int i = 0; i < 4; i++) s += h[t * 4 + i];
    __shared__ unsigned long long sh[8];
#pragma unroll
    for (int o = 16; o > 0; o >>= 1) s += __shfl_down_sync(0xffffffffu, s, o);
    if ((t & 31) == 0) sh[t >> 5] = s;
    __syncthreads();
    if (t == 0) {
        unsigned long long v = 0;
#pragma unroll
        for (int w = 0; w < 8; w++) v += sh[w];
        part[blockIdx.x] = v;
    }
}

// evaluate lovasz contributions per chunk (descending err); grid = CDIM*64, block 256
__global__ void k_loveval(const unsigned long long* __restrict__ hist,
                          const unsigned long long* __restrict__ part,
                          const int* __restrict__ gts,
                          double* __restrict__ classLoss) {
    int c = blockIdx.x >> 6, chunk = blockIdx.x & 63;
    int gi = gts[c];
    if (gi == 0) return;   // absent class: excluded by lovreduce anyway
    float g = (float)gi;
    int t = threadIdx.x;
    __shared__ unsigned long long shOff;
    __shared__ unsigned long long shWarp[8];
    __shared__ double shD[8];
    if (t == 0) {
        unsigned long long o = 0;
        for (int k = chunk + 1; k < 64; k++) o += part[c * 64 + k];
        shOff = o;
    }
    const unsigned long long* h = hist + (size_t)c * NB + chunk * 1024;
    // thread t covers descending local positions 4t..4t+3 -> bins 1023-4t ...
    unsigned long long v[4]; unsigned long long tot = 0;
#pragma unroll
    for (int i = 0; i < 4; i++) { v[i] = h[1023 - (4 * t + i)]; tot += v[i]; }
    // exclusive scan over threads (ascending t = descending err)
    unsigned long long incl = tot;
#pragma unroll
    for (int o = 1; o < 32; o <<= 1) {
        unsigned long long u = __shfl_up_sync(0xffffffffu, incl, o);
        if ((t & 31) >= o) incl += u;
    }
    if ((t & 31) == 31) shWarp[t >> 5] = incl;
    __syncthreads();
    unsigned long long warpOff = 0;
    for (int w = 0; w < (t >> 5); w++) warpOff += shWarp[w];
    unsigned long long excl = shOff + warpOff + (incl - tot);
    unsigned long long P = excl >> 32, F = excl & 0xFFFFFFFFull;
    double acc = 0.0;
#pragma unroll
    for (int i = 0; i < 4; i++) {
        unsigned long long nb = v[i] >> 32, fb = v[i] & 0xFFFFFFFFull;
        if (nb) {
            int bin = chunk * 1024 + 1023 - (4 * t + i);
            float e = (float)bin * (1.0f / QL);
            float Pf = (float)P, Ff = (float)F;
            float Js = 1.f - (g - Ff) / (g + Pf - Ff);          // J(0)=0 when P=0
            float Pe = (float)(P + nb), Fe = (float)(F + fb);
            float Je = 1.f - (g - Fe) / (g + Pe - Fe);
            acc += (double)(e * (Je - Js));
            P += nb; F += fb;
        }
    }
#pragma unroll
    for (int o = 16; o > 0; o >>= 1) acc += __shfl_down_sync(0xffffffffu, acc, o);
    if ((t & 31) == 0) shD[t >> 5] = acc;
    __syncthreads();
    if (t == 0) {
        double s = 0.0;
#pragma unroll
        for (int w = 0; w < 8; w++) s += shD[w];
        atomicAdd(&classLoss[c], s);
    }
}

__global__ void k_lovreduce(float w, const int* __restrict__ gts,
                            const double* __restrict__ classLoss) {
    int tid = threadIdx.x;
    double s = 0.0; int pc = 0;
    if (tid < CDIM && gts[tid] > 0) { s = classLoss[tid]; pc = 1; }
#pragma unroll
    for (int o = 16; o > 0; o >>= 1) {
        s += __shfl_down_sync(0xffffffffu, s, o);
        pc += __shfl_down_sync(0xffffffffu, pc, o);
    }
    if (tid == 0) {
        int d = pc > 0 ? pc : 1;
        atomicAdd(&g_loss, (double)w * s / (double)d);
    }
}

__global__ void k_kl(double w, const float* __restrict__ fpred,
                     const float* __restrict__ pred3d, const int* __restrict__ idxArr) {
    int r = blockIdx.x * blockDim.x + threadIdx.x;
    double local = 0.0;
    if (r < NIMG) {
        float zf[CDIM], zp[CDIM];
        int vi = idxArr[r];
#pragma unroll
        for (int c = 0; c < CDIM; c++) {
            zf[c] = fpred[(size_t)r * CDIM + c];
            zp[c] = pred3d[(size_t)vi * CDIM + c];
        }
        float mf = zf[0], mp = zp[0];
#pragma unroll
        for (int c = 1; c < CDIM; c++) { mf = fmaxf(mf, zf[c]); mp = fmaxf(mp, zp[c]); }
        float sf = 0.f, sp = 0.f;
#pragma unroll
        for (int c = 0; c < CDIM; c++) { sf += expf(zf[c] - mf); sp += expf(zp[c] - mp); }
        float lsf = logf(sf), lsp = logf(sp);
        float acc = 0.f;
#pragma unroll
        for (int c = 0; c < CDIM; c++) {
            float lp = zf[c] - mf - lsf;
            float p = expf(lp);
            float lq = zp[c] - mp - lsp;
            acc += p * (lp - lq);
        }
        local = (double)acc;
    }
    double tot = blockReduceSumD(local);
    if (threadIdx.x == 0) atomicAdd(&g_loss, tot * w);
}

__global__ void k_finish(float* out) { out[0] = (float)g_loss; }

// ------------------------- host -------------------------
static inline int ceildiv(int a, int b) { return (a + b - 1) / b; }

extern "C" void kernel_launch(void* const* d_in, const int* in_sizes, int n_in,
                              void* d_out, int out_size) {
    const float* img_feat = (const float*)d_in[0];
    const float* pts_feat = (const float*)d_in[1];
    const int*   coors_inv = (const int*)d_in[2];
    const int*   labels   = (const int*)d_in[3];
    const int*   img_label = (const int*)d_in[4];
    const int*   p2img    = (const int*)d_in[5];
    const float* w3a = (const float*)d_in[6];  const float* b3a = (const float*)d_in[7];
    const float* w3b = (const float*)d_in[8];  const float* b3b = (const float*)d_in[9];
    const float* wfa = (const float*)d_in[10]; const float* bfa = (const float*)d_in[11];
    const float* wfb = (const float*)d_in[12]; const float* bfb = (const float*)d_in[13];
    const float* fc1w = (const float*)d_in[14]; const float* fc1b = (const float*)d_in[15];
    const float* fc2w = (const float*)d_in[16]; const float* fc2b = (const float*)d_in[17];
    const float* fc3w = (const float*)d_in[18]; const float* fc3b = (const float*)d_in[19];
    const float* c1w = (const float*)d_in[20]; const float* c1b = (const float*)d_in[21];
    const float* bn1g = (const float*)d_in[22]; const float* bn1b = (const float*)d_in[23];
    const float* c2w = (const float*)d_in[24]; const float* c2b = (const float*)d_in[25];
    const float* bn2g = (const float*)d_in[26]; const float* bn2b = (const float*)d_in[27];
    const float* clw1 = (const float*)d_in[28]; const float* clb1 = (const float*)d_in[29];
    const float* clw2 = (const float*)d_in[30]; const float* clb2 = (const float*)d_in[31];

    void *pv;
    cudaGetSymbolAddress(&pv, g_H1);       float* H1b = (float*)pv;
    cudaGetSymbolAddress(&pv, g_pred3d);   float* predb = (float*)pv;
    cudaGetSymbolAddress(&pv, g_counts);   int* countsb = (int*)pv;
    cudaGetSymbolAddress(&pv, g_voxlab);   int* voxlabb = (int*)pv;
    cudaGetSymbolAddress(&pv, g_idx);      int* idxb = (int*)pv;
    cudaGetSymbolAddress(&pv, g_P);        float* Pb = (float*)pv;
    cudaGetSymbolAddress(&pv, g_a1);       float* a1b = (float*)pv;
    cudaGetSymbolAddress(&pv, g_a2);       float* a2b = (float*)pv;
    cudaGetSymbolAddress(&pv, g_attw);     float* attwb = (float*)pv;
    cudaGetSymbolAddress(&pv, g_y1);       float* y1b = (float*)pv;
    cudaGetSymbolAddress(&pv, g_y2);       float* y2b = (float*)pv;
    cudaGetSymbolAddress(&pv, g_fpred);    float* fpredb = (float*)pv;
    cudaGetSymbolAddress(&pv, g_stats);    float* statsb = (float*)pv;
    cudaGetSymbolAddress(&pv, g_hist);     unsigned long long* histb = (unsigned long long*)pv;
    cudaGetSymbolAddress(&pv, g_part);     unsigned long long* partb = (unsigned long long*)pv;
    cudaGetSymbolAddress(&pv, g_classLoss);double* clsb = (double*)pv;
    cudaGetSymbolAddress(&pv, g_gts_vox);  int* gtsvoxb = (int*)pv;
    cudaGetSymbolAddress(&pv, g_HF);       float* HF = (float*)pv;
    cudaGetSymbolAddress(&pv, g_fpredF);   float* fpredF = (float*)pv;
    cudaGetSymbolAddress(&pv, g_feats);    float* feats = (float*)pv;
    cudaGetSymbolAddress(&pv, g_gts_img);  int* gtsimg = (int*)pv;
    cudaGetSymbolAddress(&pv, g_loss);     void* p_loss = pv;

    static cudaStream_t strS[NSCALE] = {};
    static cudaEvent_t evFork = nullptr;
    static cudaEvent_t evPred[NSCALE] = {}, evFpred[NSCALE] = {}, evFeats[NSCALE] = {};
    static cudaEvent_t evEnd[NSCALE] = {};
    if (!strS[0]) {
        for (int s = 0; s < NSCALE; s++) {
            cudaStreamCreateWithFlags(&strS[s], cudaStreamNonBlocking);
            cudaEventCreateWithFlags(&evPred[s], cudaEventDisableTiming);
            cudaEventCreateWithFlags(&evFpred[s], cudaEventDisableTiming);
            cudaEventCreateWithFlags(&evFeats[s], cudaEventDisableTiming);
            cudaEventCreateWithFlags(&evEnd[s], cudaEventDisableTiming);
        }
        cudaEventCreateWithFlags(&evFork, cudaEventDisableTiming);
    }

    cudaStream_t st0 = 0;
    // pre-fork setup on legacy stream
    cudaMemsetAsync(p_loss, 0, sizeof(double), st0);
    cudaMemsetAsync(gtsimg, 0, CDIM * sizeof(int), st0);
    cudaMemsetAsync(countsb, 0, (size_t)NSCALE * NVOX * CDIM * sizeof(int), st0);
    cudaMemsetAsync(gtsvoxb, 0, NSCALE * CDIM * sizeof(int), st0);
    cudaMemsetAsync(histb, 0, (size_t)NLOSS * CDIM * NB * sizeof(unsigned long long), st0);
    cudaMemsetAsync(clsb, 0, NLOSS * CDIM * sizeof(double), st0);
    k_hist<<<ceildiv(NIMG, 256), 256, 0, st0>>>(img_label, NIMG, gtsimg);
    cudaEventRecord(evFork, st0);
    for (int s = 0; s < NSCALE; s++) cudaStreamWaitEvent(strS[s], evFork, 0);

    // loss-instance buffers: 0=vox0, 1=vox1, 2=fuse0, 3=fuse1, 4=final
    auto hist = [&](int i) { return histb + (size_t)i * CDIM * NB; };
    auto part = [&](int i) { return partb + (size_t)i * CDIM * 64; };
    auto cls  = [&](int i) { return clsb + (size_t)i * CDIM; };
    auto hist_lovasz = [&](int li, const float* logits, const int* lab, int n,
                           float weight, const int* gts, cudaStream_t st) {
        k_softmax_hist<<<ceildiv(n, 256), 256, 0, st>>>(logits, lab, n, weight, hist(li));
        k_lovpart<<<CDIM * 64, 256, 0, st>>>(hist(li), part(li));
        k_loveval<<<CDIM * 64, 256, 0, st>>>(hist(li), part(li), gts, cls(li));
        k_lovreduce<<<1, 32, 0, st>>>(weight, gts, cls(li));
    };

    // ---- fusion chains (one per created stream) ----
    for (int s = 0; s < NSCALE; s++) {
        cudaStream_t sF = strS[s];
        const float* pts_s = pts_feat + (size_t)s * NVOX * HDIM;
        const float* img_s = img_feat + (size_t)s * NIMG * HDIM;
        const int* coors_s = coors_inv + (size_t)s * NPTS;
        float* H1 = H1b + (size_t)s * NVOX * HIDD;
        float* pred = predb + (size_t)s * NVOX * CDIM;
        int* idxArr = idxb + (size_t)s * NIMG;
        float* P = Pb + (size_t)s * NIMG * HDIM;
        float* a1 = a1b + (size_t)s * NIMG * MIDD;
        float* a2 = a2b + (size_t)s * NIMG * MIDD;
        float* attw = attwb + (size_t)s * NIMG * 2;
        float* y1 = y1b + (size_t)s * NIMG * HDIM;
        float* y2 = y2b + (size_t)s * NIMG * HDIM;
        float* fpred = fpredb + (size_t)s * NIMG * CDIM;
        float* stats = statsb + (size_t)s * 4 * HDIM;

        k_gemm2<128, 128, 8, 8, true><<<dim3(1, ceildiv(NVOX, 128)), 256, 0, sF>>>(
            pts_s, HDIM, w3a + (size_t)s * HDIM * HIDD, b3a + s * HIDD, H1, NVOX, HIDD, HDIM);
        k_gemm<64, 32, 4, 2, false><<<dim3(1, ceildiv(NVOX, 64)), 256, 0, sF>>>(
            H1, HIDD, w3b + (size_t)s * HIDD * CDIM, b3b + s * CDIM, pred, NVOX, CDIM, HIDD);
        cudaEventRecord(evPred[s], sF);

        k_idxgather<<<ceildiv(NIMG * HDIM, 256), 256, 0, sF>>>(pts_s, coors_s, p2img, idxArr, P);
        k_gemm<64, 32, 4, 2, false><<<dim3(1, ceildiv(NIMG, 64)), 256, 0, sF>>>(
            P, HDIM, fc1w + (size_t)s * HDIM * MIDD, fc1b + s * MIDD, a1, NIMG, MIDD, HDIM);
        k_gemm<64, 32, 4, 2, false><<<dim3(1, ceildiv(NIMG, 64)), 256, 0, sF>>>(
            img_s, HDIM, fc2w + (size_t)s * HDIM * MIDD, fc2b + s * MIDD, a2, NIMG, MIDD, HDIM);
        k_att<<<ceildiv(NIMG, 256), 256, 0, sF>>>(a1, a2, attw,
            fc3w + (size_t)s * 2 * MIDD * 2, fc3b + s * 2);
        k_gemm2<128, 64, 8, 4, false><<<dim3(1, ceildiv(NIMG, 128)), 256, 0, sF>>>(
            P, HDIM, c1w + (size_t)s * HDIM * HDIM, c1b + s * HDIM, y1, NIMG, HDIM, HDIM);
        k_gemm2<128, 64, 8, 4, false><<<dim3(1, ceildiv(NIMG, 128)), 256, 0, sF>>>(
            img_s, HDIM, c2w + (size_t)s * HDIM * HDIM, c2b + s * HDIM, y2, NIMG, HDIM, HDIM);
        cudaMemsetAsync(stats, 0, 4 * HDIM * sizeof(float), sF);
        k_colstats<<<ceildiv(NIMG, ROWSPB), 256, 0, sF>>>(y1, stats, 0);
        k_colstats<<<ceildiv(NIMG, ROWSPB), 256, 0, sF>>>(y2, stats, 128);
        k_fuse<<<ceildiv(NIMG * HDIM, 256), 256, 0, sF>>>(y1, y2, attw, stats,
            bn1g + s * HDIM, bn1b + s * HDIM, bn2g + s * HDIM, bn2b + s * HDIM, s);
        cudaEventRecord(evFeats[s], sF);

        k_gemm2<128, 128, 8, 8, true><<<dim3(1, ceildiv(NIMG, 128)), 256, 0, sF>>>(
            feats + s * HDIM, 2 * HDIM, wfa + (size_t)s * HDIM * HIDD, bfa + s * HIDD,
            H1, NIMG, HIDD, HDIM);
        k_gemm<64, 32, 4, 2, false><<<dim3(1, ceildiv(NIMG, 64)), 256, 0, sF>>>(
            H1, HIDD, wfb + (size_t)s * HIDD * CDIM, bfb + s * CDIM, fpred, NIMG, CDIM, HIDD);
        cudaEventRecord(evFpred[s], sF);
        k_kl<<<ceildiv(NIMG, 256), 256, 0, sF>>>(0.025 / ((double)NIMG * (double)CDIM),
                                                 fpred, pred, idxArr);
    }

    // ---- loss tails (cross-assigned) ----
    // stream 0: vox-loss scale 1 + final classifier chain
    {
        cudaStream_t st = strS[0];
        int o = 1;
        k_scatter<<<ceildiv(NPTS, 256), 256, 0, st>>>(
            coors_inv + (size_t)o * NPTS, labels, countsb + (size_t)o * NVOX * CDIM);
        k_argmax<<<ceildiv(NVOX, 256), 256, 0, st>>>(
            countsb + (size_t)o * NVOX * CDIM, voxlabb + (size_t)o * NVOX,
            gtsvoxb + (size_t)o * CDIM);
        cudaStreamWaitEvent(st, evPred[o], 0);
        hist_lovasz(1, predb + (size_t)o * NVOX * CDIM, voxlabb + (size_t)o * NVOX,
                    NVOX, 1.0f, gtsvoxb + (size_t)o * CDIM, st);

        cudaStreamWaitEvent(st, evFeats[1], 0);   // feats slice 0 produced in-stream
        k_gemm2<128, 128, 8, 8, true><<<dim3(1, ceildiv(NIMG, 128)), 256, 0, st>>>(
            feats, 2 * HDIM, clw1, clb1, HF, NIMG, HIDD, 2 * HDIM);
        k_gemm<64, 32, 4, 2, false><<<dim3(1, ceildiv(NIMG, 64)), 256, 0, st>>>(
            HF, HIDD, clw2, clb2, fpredF, NIMG, CDIM, HIDD);
        hist_lovasz(4, fpredF, img_label, NIMG, 1.0f, gtsimg, st);
        cudaEventRecord(evEnd[0], st);
    }
    // stream 1: vox-loss scale 0 + both fuse losses
    {
        cudaStream_t st = strS[1];
        int o = 0;
        k_scatter<<<ceildiv(NPTS, 256), 256, 0, st>>>(
            coors_inv + (size_t)o * NPTS, labels, countsb + (size_t)o * NVOX * CDIM);
        k_argmax<<<ceildiv(NVOX, 256), 256, 0, st>>>(
            countsb + (size_t)o * NVOX * CDIM, voxlabb + (size_t)o * NVOX,
            gtsvoxb + (size_t)o * CDIM);
        cudaStreamWaitEvent(st, evPred[o], 0);
        hist_lovasz(0, predb, voxlabb, NVOX, 1.0f, gtsvoxb, st);

        cudaStreamWaitEvent(st, evFpred[0], 0);
        hist_lovasz(2, fpredb, img_label, NIMG, 0.5f, gtsimg, st);
        hist_lovasz(3, fpredb + (size_t)1 * NIMG * CDIM, img_label, NIMG, 0.5f, gtsimg, st);
        cudaEventRecord(evEnd[1], st);
    }

    for (int s = 0; s < NSCALE; s++) cudaStreamWaitEvent(st0, evEnd[s], 0);
    k_finish<<<1, 1, 0, st0>>>((float*)d_out);
}